// round 9
// baseline (speedup 1.0000x reference)
#include <cuda_runtime.h>
#include <stdint.h>
#include <math.h>

// ---------------------------------------------------------------------------
// ViT-Base forward: B=32, S=197, D=768, FF=3072, L=12, heads 12x64, out [32,1000]
// GEMMs: tf32 mma.sync (m16n8k8), fp32 accumulate, double-buffered smem.
// Attention/LN/GELU: exact fp32.
// ---------------------------------------------------------------------------

static constexpr int BATCH = 32, SEQ = 197, DIM = 768, FFD = 3072, LAYERS = 12;
static constexpr int NP = 196, NCLS = 1000;
static constexpr int ROWS  = BATCH * SEQ;   // 6304
static constexpr int PROWS = BATCH * NP;    // 6272

static constexpr size_t S_PATCH = (size_t)PROWS * DIM;
static constexpr size_t S_ACT   = (size_t)ROWS * DIM;
static constexpr size_t S_MLP   = (size_t)ROWS * FFD;
static constexpr size_t S_CLS   = (size_t)32 * DIM;

// One big static scratch (allowed; no cudaMalloc anywhere).
__device__ float g_scratch[S_PATCH + 6 * S_ACT + S_MLP + S_CLS];

// Attention dynamic smem: K[197][65] + V[197][65] + probs[8 warps][4][200]
static constexpr int ATTN_SMEM_FLOATS = 2 * 197 * 65 + 8 * 4 * 200;
static constexpr int ATTN_SMEM = ATTN_SMEM_FLOATS * 4;  // 128040 B

// GEMM double-buffered smem: 2 * (128*36 + 32*136) floats = 71680 B
static constexpr int AS_SZ = 128 * 36;
static constexpr int BS_SZ = 32 * 136;
static constexpr int GEMM_SMEM = 2 * (AS_SZ + BS_SZ) * 4;

// ---------------------------------------------------------------------------
// helpers
// ---------------------------------------------------------------------------
__device__ __forceinline__ float to_tf32(float x) {
    unsigned u;
    asm("cvt.rna.tf32.f32 %0, %1;" : "=r"(u) : "f"(x));
    return __uint_as_float(u);
}

__device__ __forceinline__ void mma_16n8k8(float c[4], const unsigned a[4], const unsigned b[2]) {
    asm volatile(
        "mma.sync.aligned.m16n8k8.row.col.f32.tf32.tf32.f32 "
        "{%0,%1,%2,%3}, {%4,%5,%6,%7}, {%8,%9}, {%0,%1,%2,%3};\n"
        : "+f"(c[0]), "+f"(c[1]), "+f"(c[2]), "+f"(c[3])
        : "r"(a[0]), "r"(a[1]), "r"(a[2]), "r"(a[3]), "r"(b[0]), "r"(b[1]));
}

// ---------------------------------------------------------------------------
// GEMM: C[M,N] = A[M,K] @ B[K,N] + bias  (+residual | +GELU)
// Block tile 128x128x32, 256 threads, warp grid 2(M)x4(N), warp tile 64x32.
// Double-buffered smem: one __syncthreads per k-iteration.
// EPI: 0 = bias, 1 = bias + residual R, 2 = bias + exact GELU
// ---------------------------------------------------------------------------
template <int EPI>
__global__ __launch_bounds__(256, 1)
void gemm_tf32(const float* __restrict__ A, const float* __restrict__ B,
               const float* __restrict__ bias, const float* R,
               float* C, int M, int N, int K)
{
    extern __shared__ float dsm[];
    float* Asb = dsm;                 // 2 x [128][36]
    float* Bsb = dsm + 2 * AS_SZ;     // 2 x [32][136]

    const int tid = threadIdx.x, lane = tid & 31, wid = tid >> 5;
    const int wm = wid >> 2, wn = wid & 3;
    const int bm = blockIdx.y << 7, bn = blockIdx.x << 7;

    // global->reg staging indices
    const int ar = tid >> 3, ac = (tid & 7) << 2;      // A: 32 rows/pass, 8 f4 per row
    const int bkr = tid >> 5, bc = (tid & 31) << 2;    // B: 8 k-rows/pass, 32 f4 per row

    float4 ra[4], rb[4];

    auto gload = [&](int kt) {
        const int k0 = kt << 5;
#pragma unroll
        for (int p = 0; p < 4; p++) {
            int gr = bm + (p << 5) + ar;
            if (gr < M) ra[p] = *reinterpret_cast<const float4*>(A + (size_t)gr * K + k0 + ac);
            else        ra[p] = make_float4(0.f, 0.f, 0.f, 0.f);
        }
#pragma unroll
        for (int p = 0; p < 4; p++) {
            int gk = k0 + (p << 3) + bkr;          // K is always a multiple of 32
            int gn = bn + bc;
            const float* src = B + (size_t)gk * N + gn;
            if (gn + 3 < N) {
                rb[p] = *reinterpret_cast<const float4*>(src);
            } else {
                float4 v;
                v.x = (gn     < N) ? src[0] : 0.f;
                v.y = (gn + 1 < N) ? src[1] : 0.f;
                v.z = (gn + 2 < N) ? src[2] : 0.f;
                v.w = 0.f;
                rb[p] = v;
            }
        }
    };

    auto sstore = [&](int buf) {
        float* As = Asb + buf * AS_SZ;
        float* Bs = Bsb + buf * BS_SZ;
#pragma unroll
        for (int p = 0; p < 4; p++) {
            float4 v = ra[p];
            v.x = to_tf32(v.x); v.y = to_tf32(v.y); v.z = to_tf32(v.z); v.w = to_tf32(v.w);
            *reinterpret_cast<float4*>(&As[((p << 5) + ar) * 36 + ac]) = v;
        }
#pragma unroll
        for (int p = 0; p < 4; p++) {
            float4 v = rb[p];
            v.x = to_tf32(v.x); v.y = to_tf32(v.y); v.z = to_tf32(v.z); v.w = to_tf32(v.w);
            *reinterpret_cast<float4*>(&Bs[((p << 3) + bkr) * 136 + bc]) = v;
        }
    };

    float acc[4][4][4];
#pragma unroll
    for (int mt = 0; mt < 4; mt++)
#pragma unroll
        for (int nt = 0; nt < 4; nt++)
#pragma unroll
            for (int i = 0; i < 4; i++) acc[mt][nt][i] = 0.f;

    gload(0);
    sstore(0);
    __syncthreads();

    const int KT = K >> 5;
    for (int kt = 0; kt < KT; kt++) {
        const int buf = kt & 1;
        if (kt + 1 < KT) gload(kt + 1);   // overlap next-tile global loads with compute
        const float* As = Asb + buf * AS_SZ;
        const float* Bs = Bsb + buf * BS_SZ;
#pragma unroll
        for (int ks = 0; ks < 4; ks++) {
            const int ko = ks << 3;
            unsigned af[4][4], bf[4][2];
#pragma unroll
            for (int mt = 0; mt < 4; mt++) {
                const float* ap = &As[(wm * 64 + mt * 16 + (lane >> 2)) * 36 + ko + (lane & 3)];
                af[mt][0] = __float_as_uint(ap[0]);
                af[mt][1] = __float_as_uint(ap[8 * 36]);
                af[mt][2] = __float_as_uint(ap[4]);
                af[mt][3] = __float_as_uint(ap[8 * 36 + 4]);
            }
#pragma unroll
            for (int nt = 0; nt < 4; nt++) {
                const float* bp = &Bs[(ko + (lane & 3)) * 136 + wn * 32 + nt * 8 + (lane >> 2)];
                bf[nt][0] = __float_as_uint(bp[0]);
                bf[nt][1] = __float_as_uint(bp[4 * 136]);
            }
#pragma unroll
            for (int mt = 0; mt < 4; mt++)
#pragma unroll
                for (int nt = 0; nt < 4; nt++)
                    mma_16n8k8(acc[mt][nt], af[mt], bf[nt]);
        }
        // Write NEXT tile into the other buffer. Safe: no warp reaches this
        // store for iteration kt+1 until every warp passed the barrier below
        // for iteration kt (i.e., finished computing from buf kt&1).
        if (kt + 1 < KT) sstore(buf ^ 1);
        __syncthreads();
    }

    // epilogue
#pragma unroll
    for (int mt = 0; mt < 4; mt++) {
#pragma unroll
        for (int nt = 0; nt < 4; nt++) {
            int r0 = bm + wm * 64 + mt * 16 + (lane >> 2);
            int c0 = bn + wn * 32 + nt * 8 + ((lane & 3) << 1);
#pragma unroll
            for (int i = 0; i < 4; i++) {
                int r = r0 + ((i >> 1) << 3);
                int cc = c0 + (i & 1);
                if (r < M && cc < N) {
                    float v = acc[mt][nt][i] + bias[cc];
                    if (EPI == 1) v += R[(size_t)r * N + cc];
                    if (EPI == 2) v = 0.5f * v * (1.0f + erff(v * 0.70710678118654752f));
                    C[(size_t)r * N + cc] = v;
                }
            }
        }
    }
}

// ---------------------------------------------------------------------------
// LayerNorm (custom: (x-mean)/(sqrt(var)+eps)*w + b, eps OUTSIDE sqrt), D=768
// One block of 256 threads per row; istride lets us gather CLS rows for the head.
// ---------------------------------------------------------------------------
__global__ void ln_kernel(const float* __restrict__ in, float* __restrict__ out,
                          const float* __restrict__ w, const float* __restrict__ b,
                          long long istride)
{
    const int r = blockIdx.x, tid = threadIdx.x;
    const float* x = in + (size_t)r * istride;
    float* o = out + (size_t)r * 768;

    float v0 = x[tid], v1 = x[tid + 256], v2 = x[tid + 512];
    float s = v0 + v1 + v2;
    float s2 = v0 * v0 + v1 * v1 + v2 * v2;
#pragma unroll
    for (int ofs = 16; ofs; ofs >>= 1) {
        s  += __shfl_xor_sync(0xffffffffu, s,  ofs);
        s2 += __shfl_xor_sync(0xffffffffu, s2, ofs);
    }
    __shared__ float sa[8], sb[8];
    __shared__ float s_mean, s_rs;
    if ((tid & 31) == 0) { sa[tid >> 5] = s; sb[tid >> 5] = s2; }
    __syncthreads();
    if (tid == 0) {
        float S = 0.f, S2 = 0.f;
#pragma unroll
        for (int i = 0; i < 8; i++) { S += sa[i]; S2 += sb[i]; }
        float mean = S * (1.0f / 768.0f);
        float var  = fmaxf(S2 * (1.0f / 768.0f) - mean * mean, 0.0f);
        s_mean = mean;
        s_rs   = 1.0f / (sqrtf(var) + 1e-5f);
    }
    __syncthreads();
    float mean = s_mean, rs = s_rs;
    o[tid]       = (v0 - mean) * rs * w[tid]       + b[tid];
    o[tid + 256] = (v1 - mean) * rs * w[tid + 256] + b[tid + 256];
    o[tid + 512] = (v2 - mean) * rs * w[tid + 512] + b[tid + 512];
}

// ---------------------------------------------------------------------------
// img_to_patch gather: x[B,3,224,224] -> P[6272, 768]  (feature = c*256+py*16+px)
// ---------------------------------------------------------------------------
__global__ void gather_patches(const float* __restrict__ x, float* __restrict__ p)
{
    int idx = blockIdx.x * 256 + threadIdx.x;
    if (idx >= PROWS * DIM) return;
    int row = idx / 768, kk = idx - row * 768;
    int b = row / 196, pr = row - b * 196;
    int ph = pr / 14, pw = pr - ph * 14;
    int c = kk >> 8, r2 = kk & 255, py = r2 >> 4, px = r2 & 15;
    size_t src = ((size_t)(b * 3 + c) * 224 + (ph * 16 + py)) * 224 + (pw * 16 + px);
    p[idx] = x[src];
}

// h[b,0,:]=cls+pos[0]; h[b,1+n,:]=emb[b*196+n]+pos[1+n]
__global__ void assemble_h(const float* __restrict__ emb, const float* __restrict__ cls,
                           const float* __restrict__ pos, float* __restrict__ h)
{
    int idx = blockIdx.x * 256 + threadIdx.x;
    if (idx >= ROWS * DIM) return;
    int row = idx / 768, d = idx - row * 768;
    int b = row / 197, s = row - b * 197;
    float v = (s == 0) ? cls[d] : emb[((size_t)b * 196 + (s - 1)) * 768 + d];
    h[idx] = v + pos[s * 768 + d];
}

// ---------------------------------------------------------------------------
// Fused attention: one block per (b,h). K,V staged in smem (stride 65, conflict-
// free), 4-query register groups per warp, per-warp probs row, softmax + AV fused.
// scores = QK^T/8, softmax over keys, out = P@V. All fp32.
// ---------------------------------------------------------------------------
__global__ __launch_bounds__(256, 1)
void attn_kernel(const float* __restrict__ Q, const float* __restrict__ K,
                 const float* __restrict__ V, float* __restrict__ Y)
{
    extern __shared__ float sm[];
    float* Ks = sm;                 // 197*65
    float* Vs = Ks + 197 * 65;      // 197*65
    float* Ps = Vs + 197 * 65;      // 8*4*200

    const int h = blockIdx.x, b = blockIdx.y;
    const int tid = threadIdx.x, wid = tid >> 5, lane = tid & 31;
    const size_t base = (size_t)b * 197 * 768 + h * 64;

    for (int i = tid; i < 197 * 64; i += 256) {
        int s = i >> 6, d = i & 63;
        Ks[s * 65 + d] = K[base + (size_t)s * 768 + d];
        Vs[s * 65 + d] = V[base + (size_t)s * 768 + d];
    }
    __syncthreads();

    for (int g = wid; g < 50; g += 8) {          // 50 groups of 4 queries (last has 1)
        int q0 = g * 4;
        int nq = min(4, 197 - q0);
        float qr[4][2];
#pragma unroll
        for (int qi = 0; qi < 4; qi++) {
            if (qi < nq) {
                const float* qp = Q + base + (size_t)(q0 + qi) * 768;
                qr[qi][0] = qp[lane];
                qr[qi][1] = qp[lane + 32];
            } else {
                qr[qi][0] = 0.f; qr[qi][1] = 0.f;
            }
        }
        float* Pw = Ps + (wid * 4) * 200;

        // ---- scores: each lane owns one key per 32-chunk; q broadcast via shfl
#pragma unroll 1
        for (int c = 0; c < 7; c++) {
            int j = c * 32 + lane;
            int jc = (j < 197) ? j : 196;
            const float* kp = Ks + jc * 65;
            float a0 = 0.f, a1 = 0.f, a2 = 0.f, a3 = 0.f;
#pragma unroll
            for (int d = 0; d < 64; d++) {
                float kd = kp[d];
                float q0v = __shfl_sync(0xffffffffu, qr[0][d >> 5], d & 31);
                float q1v = __shfl_sync(0xffffffffu, qr[1][d >> 5], d & 31);
                float q2v = __shfl_sync(0xffffffffu, qr[2][d >> 5], d & 31);
                float q3v = __shfl_sync(0xffffffffu, qr[3][d >> 5], d & 31);
                a0 = fmaf(q0v, kd, a0);
                a1 = fmaf(q1v, kd, a1);
                a2 = fmaf(q2v, kd, a2);
                a3 = fmaf(q3v, kd, a3);
            }
            if (j < 197) {
                Pw[0 * 200 + j] = a0 * 0.125f;
                Pw[1 * 200 + j] = a1 * 0.125f;
                Pw[2 * 200 + j] = a2 * 0.125f;
                Pw[3 * 200 + j] = a3 * 0.125f;
            }
        }
        __syncwarp();

        // ---- softmax per query row (unnormalized exp written back, keep 1/sum)
        float inv[4];
#pragma unroll
        for (int qi = 0; qi < 4; qi++) {
            float m = -1e30f;
            for (int j = lane; j < 197; j += 32) m = fmaxf(m, Pw[qi * 200 + j]);
#pragma unroll
            for (int o = 16; o; o >>= 1) m = fmaxf(m, __shfl_xor_sync(0xffffffffu, m, o));
            float ssum = 0.f;
            for (int j = lane; j < 197; j += 32) {
                float e = __expf(Pw[qi * 200 + j] - m);
                Pw[qi * 200 + j] = e;
                ssum += e;
            }
#pragma unroll
            for (int o = 16; o; o >>= 1) ssum += __shfl_xor_sync(0xffffffffu, ssum, o);
            inv[qi] = 1.0f / ssum;
        }
        __syncwarp();

        // ---- AV: lane owns dims (lane, lane+32)
        float o0[4] = {0.f, 0.f, 0.f, 0.f};
        float o1[4] = {0.f, 0.f, 0.f, 0.f};
#pragma unroll 1
        for (int j = 0; j < 197; j++) {
            float v0 = Vs[j * 65 + lane];
            float v1 = Vs[j * 65 + 32 + lane];
#pragma unroll
            for (int qi = 0; qi < 4; qi++) {
                float p = Pw[qi * 200 + j];
                o0[qi] = fmaf(p, v0, o0[qi]);
                o1[qi] = fmaf(p, v1, o1[qi]);
            }
        }
        for (int qi = 0; qi < nq; qi++) {
            float* yp = Y + base + (size_t)(q0 + qi) * 768;
            yp[lane]      = o0[qi] * inv[qi];
            yp[lane + 32] = o1[qi] * inv[qi];
        }
        __syncwarp();   // WAR: Pw reused by next group
    }
}

// ---------------------------------------------------------------------------
// driver
// ---------------------------------------------------------------------------
extern "C" void kernel_launch(void* const* d_in, const int* in_sizes, int n_in,
                              void* d_out, int out_size)
{
    const float* x       = (const float*)d_in[0];
    const float* patch_w = (const float*)d_in[1];
    const float* patch_b = (const float*)d_in[2];
    const float* cls_t   = (const float*)d_in[3];
    const float* pos     = (const float*)d_in[4];
    const float* ln1w    = (const float*)d_in[5];
    const float* ln1b    = (const float*)d_in[6];
    const float* wq      = (const float*)d_in[7];
    const float* bq      = (const float*)d_in[8];
    const float* wk      = (const float*)d_in[9];
    const float* bk      = (const float*)d_in[10];
    const float* wv      = (const float*)d_in[11];
    const float* bv      = (const float*)d_in[12];
    const float* wy      = (const float*)d_in[13];
    const float* by      = (const float*)d_in[14];
    const float* ln2w    = (const float*)d_in[15];
    const float* ln2b    = (const float*)d_in[16];
    const float* m1w     = (const float*)d_in[17];
    const float* m1b     = (const float*)d_in[18];
    const float* m2w     = (const float*)d_in[19];
    const float* m2b     = (const float*)d_in[20];
    const float* hlnw    = (const float*)d_in[21];
    const float* hlnb    = (const float*)d_in[22];
    const float* hw      = (const float*)d_in[23];
    const float* hb      = (const float*)d_in[24];
    float* out = (float*)d_out;

    void* sp = nullptr;
    cudaGetSymbolAddress(&sp, g_scratch);
    float* base = (float*)sp;
    float* P   = base;
    float* H   = P + S_PATCH;
    float* Z   = H + S_ACT;
    float* Qb  = Z + S_ACT;
    float* Kb  = Qb + S_ACT;
    float* Vb  = Kb + S_ACT;
    float* Yb  = Vb + S_ACT;
    float* MB  = Yb + S_ACT;
    float* CLS = MB + S_MLP;

    cudaFuncSetAttribute(attn_kernel, cudaFuncAttributeMaxDynamicSharedMemorySize, ATTN_SMEM);
    cudaFuncSetAttribute(gemm_tf32<0>, cudaFuncAttributeMaxDynamicSharedMemorySize, GEMM_SMEM);
    cudaFuncSetAttribute(gemm_tf32<1>, cudaFuncAttributeMaxDynamicSharedMemorySize, GEMM_SMEM);
    cudaFuncSetAttribute(gemm_tf32<2>, cudaFuncAttributeMaxDynamicSharedMemorySize, GEMM_SMEM);

    // patch embed
    gather_patches<<<(PROWS * DIM + 255) / 256, 256>>>(x, P);
    gemm_tf32<0><<<dim3(6, 49), 256, GEMM_SMEM>>>(P, patch_w, patch_b, nullptr, Z, PROWS, 768, 768);
    assemble_h<<<(ROWS * DIM + 255) / 256, 256>>>(Z, cls_t, pos, H);

    const dim3 gp(6, 50);     // N=768 GEMMs over 6304 rows
    const dim3 gm1(24, 50);   // N=3072
    for (int l = 0; l < LAYERS; l++) {
        ln_kernel<<<ROWS, 256>>>(H, Z, ln1w + l * 768, ln1b + l * 768, 768);
        gemm_tf32<0><<<gp, 256, GEMM_SMEM>>>(Z, wq + (size_t)l * 768 * 768, bq + l * 768, nullptr, Qb, ROWS, 768, 768);
        gemm_tf32<0><<<gp, 256, GEMM_SMEM>>>(Z, wk + (size_t)l * 768 * 768, bk + l * 768, nullptr, Kb, ROWS, 768, 768);
        gemm_tf32<0><<<gp, 256, GEMM_SMEM>>>(Z, wv + (size_t)l * 768 * 768, bv + l * 768, nullptr, Vb, ROWS, 768, 768);
        attn_kernel<<<dim3(12, 32), 256, ATTN_SMEM>>>(Qb, Kb, Vb, Yb);
        gemm_tf32<1><<<gp, 256, GEMM_SMEM>>>(Yb, wy + (size_t)l * 768 * 768, by + l * 768, H, H, ROWS, 768, 768);
        ln_kernel<<<ROWS, 256>>>(H, Z, ln2w + l * 768, ln2b + l * 768, 768);
        gemm_tf32<2><<<gm1, 256, GEMM_SMEM>>>(Z, m1w + (size_t)l * 768 * 3072, m1b + (size_t)l * 3072, nullptr, MB, ROWS, 3072, 768);
        gemm_tf32<1><<<gp, 256, GEMM_SMEM>>>(MB, m2w + (size_t)l * 3072 * 768, m2b + l * 768, H, H, ROWS, 768, 3072);
    }

    // head: LN over CLS rows (gathered via row stride 197*768), then [32,768]@[768,1000]
    ln_kernel<<<32, 256>>>(H, CLS, hlnw, hlnb, (long long)197 * 768);
    gemm_tf32<0><<<dim3(8, 1), 256, GEMM_SMEM>>>(CLS, hw, hb, nullptr, out, 32, NCLS, 768);
}

// round 11
// speedup vs baseline: 1.2677x; 1.2677x over previous
#include <cuda_runtime.h>
#include <stdint.h>
#include <math.h>

// ---------------------------------------------------------------------------
// ViT-Base forward: B=32, S=197, D=768, FF=3072, L=12, heads 12x64, out [32,1000]
// GEMMs: tf32 mma.sync (m16n8k8) + 3-stage cp.async pipeline. Operands are
// pre-rounded to tf32 (cvt.rna) by producers, so raw cp.async copies give
// numerics IDENTICAL to the R9 baseline (rel_err 8.6e-4).
// Attention/LN/GELU: exact fp32 math; tcgen05 unavailable (compute_103 target).
// ---------------------------------------------------------------------------

static constexpr int BATCH = 32, SEQ = 197, DIM = 768, FFD = 3072, LAYERS = 12;
static constexpr int NP = 196, NCLS = 1000;
static constexpr int ROWS  = BATCH * SEQ;   // 6304
static constexpr int PROWS = BATCH * NP;    // 6272

static constexpr size_t S_PATCH = (size_t)PROWS * DIM;
static constexpr size_t S_ACT   = (size_t)ROWS * DIM;
static constexpr size_t S_MLP   = (size_t)ROWS * FFD;
static constexpr size_t S_CLS   = (size_t)32 * DIM;

// Pre-rounded weight copies (tf32-in-fp32), once per launch:
static constexpr size_t S_PW  = (size_t)768 * 768;            //   589,824
static constexpr size_t S_WX  = (size_t)LAYERS * 768 * 768;   // 7,077,888 (x4: q,k,v,y)
static constexpr size_t S_M1  = (size_t)LAYERS * 768 * 3072;  // 28,311,552
static constexpr size_t S_M2  = S_M1;

__device__ float g_scratch[S_PATCH + 6 * S_ACT + S_MLP + S_CLS
                           + S_PW + 4 * S_WX + S_M1 + S_M2];

// Attention dynamic smem: K[197][65] + V[197][65] + probs[8 warps][4][200]
static constexpr int ATTN_SMEM_FLOATS = 2 * 197 * 65 + 8 * 4 * 200;
static constexpr int ATTN_SMEM = ATTN_SMEM_FLOATS * 4;  // 128040 B

// Old register-staged GEMM (head only): double-buffered smem
static constexpr int AS_SZ = 128 * 36;
static constexpr int BS_SZ = 32 * 136;
static constexpr int GEMM_SMEM_OLD = 2 * (AS_SZ + BS_SZ) * 4;  // 71680

// cp.async GEMM: 3 stages of (A 128x36f = 18432B) + (B 32x136f = 17408B)
static constexpr int CP_A_BYTES  = 128 * 36 * 4;   // 18432
static constexpr int CP_B_BYTES  = 32 * 136 * 4;   // 17408
static constexpr int CP_STAGE_B  = CP_A_BYTES + CP_B_BYTES;  // 35840
static constexpr int CP_SMEM     = 3 * CP_STAGE_B;           // 107520

// ---------------------------------------------------------------------------
// helpers
// ---------------------------------------------------------------------------
__device__ __forceinline__ float to_tf32(float x) {
    unsigned u;
    asm("cvt.rna.tf32.f32 %0, %1;" : "=r"(u) : "f"(x));
    return __uint_as_float(u);
}

__device__ __forceinline__ uint32_t smem_u32(const void* p) {
    uint32_t a;
    asm("{ .reg .u64 t; cvta.to.shared.u64 t, %1; cvt.u32.u64 %0, t; }" : "=r"(a) : "l"(p));
    return a;
}

__device__ __forceinline__ void mma_16n8k8(float c[4], const unsigned a[4], const unsigned b[2]) {
    asm volatile(
        "mma.sync.aligned.m16n8k8.row.col.f32.tf32.tf32.f32 "
        "{%0,%1,%2,%3}, {%4,%5,%6,%7}, {%8,%9}, {%0,%1,%2,%3};\n"
        : "+f"(c[0]), "+f"(c[1]), "+f"(c[2]), "+f"(c[3])
        : "r"(a[0]), "r"(a[1]), "r"(a[2]), "r"(a[3]), "r"(b[0]), "r"(b[1]));
}

__device__ __forceinline__ void cp16(uint32_t dst, const float* src, bool pred) {
    int sz = pred ? 16 : 0;
    asm volatile("cp.async.cg.shared.global [%0], [%1], 16, %2;\n"
                 :: "r"(dst), "l"(src), "r"(sz) : "memory");
}
#define CP_COMMIT() asm volatile("cp.async.commit_group;" ::: "memory")
#define CP_WAIT1()  asm volatile("cp.async.wait_group 1;" ::: "memory")

// ---------------------------------------------------------------------------
// cp.async GEMM: C[M,N] = A[M,K] @ B[K,N] + bias (+residual | +GELU)
// Requires N % 128 == 0, K % 32 == 0, operands pre-rounded to tf32.
// 256 threads, warp grid 2(M)x4(N), warp tile 64x32, 3-stage pipeline.
// EPI: 0 = bias, 1 = bias + residual R, 2 = bias + exact GELU (output rounded)
// ---------------------------------------------------------------------------
template <int EPI>
__global__ __launch_bounds__(256, 2)
void gemm_cp(const float* __restrict__ A, const float* __restrict__ B,
             const float* __restrict__ bias, const float* R,
             float* C, int M, int N, int K)
{
    extern __shared__ float dsm[];
    const uint32_t sbase = smem_u32(dsm);
    const int tid = threadIdx.x, lane = tid & 31, wid = tid >> 5;
    const int wm = wid >> 2, wn = wid & 3;
    const int bm = blockIdx.y << 7, bn = blockIdx.x << 7;

    // Issue one stage (A tile 128x32, B tile 32x128) via 8 cp.async per thread.
    auto issue = [&](int kt, int slot) {
        const int k0 = kt << 5;
        const uint32_t sa = sbase + slot * CP_STAGE_B;
#pragma unroll
        for (int i = 0; i < 4; i++) {           // A: 1024 16B-chunks / 256 thr
            int c = tid + (i << 8);
            int row = c >> 3, kc = c & 7;
            int gr = bm + row;
            cp16(sa + row * 144 + kc * 16,
                 A + (size_t)gr * K + k0 + kc * 4, gr < M);
        }
#pragma unroll
        for (int i = 0; i < 4; i++) {           // B: 1024 16B-chunks / 256 thr
            int c = tid + (i << 8);
            int kr = c >> 5, nc = c & 31;
            cp16(sa + CP_A_BYTES + kr * 544 + nc * 16,
                 B + (size_t)(k0 + kr) * N + bn + nc * 4, true);
        }
        CP_COMMIT();
    };

    float acc[4][4][4];
#pragma unroll
    for (int mt = 0; mt < 4; mt++)
#pragma unroll
        for (int nt = 0; nt < 4; nt++)
#pragma unroll
            for (int i = 0; i < 4; i++) acc[mt][nt][i] = 0.f;

    const int KT = K >> 5;                      // >= 24 for all users
    issue(0, 0);
    issue(1, 1);

    for (int kt = 0; kt < KT; kt++) {
        CP_WAIT1();                              // own stage-kt chunks done
        __syncthreads();                         // publish all threads' chunks
        const int slot = kt % 3;
        const float* As = dsm + slot * (CP_STAGE_B / 4);
        const float* Bs = As + (CP_A_BYTES / 4);
#pragma unroll
        for (int ks = 0; ks < 4; ks++) {
            const int ko = ks << 3;
            unsigned af[4][4], bf[4][2];
#pragma unroll
            for (int mt = 0; mt < 4; mt++) {
                const float* ap = &As[(wm * 64 + mt * 16 + (lane >> 2)) * 36 + ko + (lane & 3)];
                af[mt][0] = __float_as_uint(ap[0]);
                af[mt][1] = __float_as_uint(ap[8 * 36]);
                af[mt][2] = __float_as_uint(ap[4]);
                af[mt][3] = __float_as_uint(ap[8 * 36 + 4]);
            }
#pragma unroll
            for (int nt = 0; nt < 4; nt++) {
                const float* bp = &Bs[(ko + (lane & 3)) * 136 + wn * 32 + nt * 8 + (lane >> 2)];
                bf[nt][0] = __float_as_uint(bp[0]);
                bf[nt][1] = __float_as_uint(bp[4 * 136]);
            }
#pragma unroll
            for (int mt = 0; mt < 4; mt++)
#pragma unroll
                for (int nt = 0; nt < 4; nt++)
                    mma_16n8k8(acc[mt][nt], af[mt], bf[nt]);
        }
        // Refill slot (kt+2)%3 == slot of kt-1: all warps passed this iter's
        // barrier => finished compute(kt-1); WAR-safe.
        if (kt + 2 < KT) issue(kt + 2, (kt + 2) % 3);
        else             CP_COMMIT();            // empty group keeps wait math
    }

    // epilogue
#pragma unroll
    for (int mt = 0; mt < 4; mt++) {
#pragma unroll
        for (int nt = 0; nt < 4; nt++) {
            int r0 = bm + wm * 64 + mt * 16 + (lane >> 2);
            int c0 = bn + wn * 32 + nt * 8 + ((lane & 3) << 1);
#pragma unroll
            for (int i = 0; i < 4; i++) {
                int r = r0 + ((i >> 1) << 3);
                int cc = c0 + (i & 1);
                if (r < M) {
                    float v = acc[mt][nt][i] + bias[cc];
                    if (EPI == 1) v += R[(size_t)r * N + cc];
                    if (EPI == 2) {
                        v = 0.5f * v * (1.0f + erff(v * 0.70710678118654752f));
                        v = to_tf32(v);          // MB feeds mlp2 GEMM
                    }
                    C[(size_t)r * N + cc] = v;
                }
            }
        }
    }
}

// ---------------------------------------------------------------------------
// Old register-staged tf32 GEMM (head only: N=1000 tail handling, cvt at stage)
// ---------------------------------------------------------------------------
__global__ __launch_bounds__(256, 1)
void gemm_old(const float* __restrict__ A, const float* __restrict__ B,
              const float* __restrict__ bias, float* C, int M, int N, int K)
{
    extern __shared__ float dsm2[];
    float* Asb = dsm2;
    float* Bsb = dsm2 + 2 * AS_SZ;

    const int tid = threadIdx.x, lane = tid & 31, wid = tid >> 5;
    const int wm = wid >> 2, wn = wid & 3;
    const int bm = blockIdx.y << 7, bn = blockIdx.x << 7;
    const int ar = tid >> 3, ac = (tid & 7) << 2;
    const int bkr = tid >> 5, bc = (tid & 31) << 2;

    float4 ra[4], rb[4];

    auto gload = [&](int kt) {
        const int k0 = kt << 5;
#pragma unroll
        for (int p = 0; p < 4; p++) {
            int gr = bm + (p << 5) + ar;
            if (gr < M) ra[p] = *reinterpret_cast<const float4*>(A + (size_t)gr * K + k0 + ac);
            else        ra[p] = make_float4(0.f, 0.f, 0.f, 0.f);
        }
#pragma unroll
        for (int p = 0; p < 4; p++) {
            int gk = k0 + (p << 3) + bkr;
            int gn = bn + bc;
            const float* src = B + (size_t)gk * N + gn;
            if (gn + 3 < N) {
                rb[p] = *reinterpret_cast<const float4*>(src);
            } else {
                float4 v;
                v.x = (gn     < N) ? src[0] : 0.f;
                v.y = (gn + 1 < N) ? src[1] : 0.f;
                v.z = (gn + 2 < N) ? src[2] : 0.f;
                v.w = 0.f;
                rb[p] = v;
            }
        }
    };
    auto sstore = [&](int buf) {
        float* As = Asb + buf * AS_SZ;
        float* Bs = Bsb + buf * BS_SZ;
#pragma unroll
        for (int p = 0; p < 4; p++) {
            float4 v = ra[p];
            v.x = to_tf32(v.x); v.y = to_tf32(v.y); v.z = to_tf32(v.z); v.w = to_tf32(v.w);
            *reinterpret_cast<float4*>(&As[((p << 5) + ar) * 36 + ac]) = v;
        }
#pragma unroll
        for (int p = 0; p < 4; p++) {
            float4 v = rb[p];
            v.x = to_tf32(v.x); v.y = to_tf32(v.y); v.z = to_tf32(v.z); v.w = to_tf32(v.w);
            *reinterpret_cast<float4*>(&Bs[((p << 3) + bkr) * 136 + bc]) = v;
        }
    };

    float acc[4][4][4];
#pragma unroll
    for (int mt = 0; mt < 4; mt++)
#pragma unroll
        for (int nt = 0; nt < 4; nt++)
#pragma unroll
            for (int i = 0; i < 4; i++) acc[mt][nt][i] = 0.f;

    gload(0); sstore(0); __syncthreads();
    const int KT = K >> 5;
    for (int kt = 0; kt < KT; kt++) {
        const int buf = kt & 1;
        if (kt + 1 < KT) gload(kt + 1);
        const float* As = Asb + buf * AS_SZ;
        const float* Bs = Bsb + buf * BS_SZ;
#pragma unroll
        for (int ks = 0; ks < 4; ks++) {
            const int ko = ks << 3;
            unsigned af[4][4], bf[4][2];
#pragma unroll
            for (int mt = 0; mt < 4; mt++) {
                const float* ap = &As[(wm * 64 + mt * 16 + (lane >> 2)) * 36 + ko + (lane & 3)];
                af[mt][0] = __float_as_uint(ap[0]);
                af[mt][1] = __float_as_uint(ap[8 * 36]);
                af[mt][2] = __float_as_uint(ap[4]);
                af[mt][3] = __float_as_uint(ap[8 * 36 + 4]);
            }
#pragma unroll
            for (int nt = 0; nt < 4; nt++) {
                const float* bp = &Bs[(ko + (lane & 3)) * 136 + wn * 32 + nt * 8 + (lane >> 2)];
                bf[nt][0] = __float_as_uint(bp[0]);
                bf[nt][1] = __float_as_uint(bp[4 * 136]);
            }
#pragma unroll
            for (int mt = 0; mt < 4; mt++)
#pragma unroll
                for (int nt = 0; nt < 4; nt++)
                    mma_16n8k8(acc[mt][nt], af[mt], bf[nt]);
        }
        if (kt + 1 < KT) sstore(buf ^ 1);
        __syncthreads();
    }
#pragma unroll
    for (int mt = 0; mt < 4; mt++)
#pragma unroll
        for (int nt = 0; nt < 4; nt++) {
            int r0 = bm + wm * 64 + mt * 16 + (lane >> 2);
            int c0 = bn + wn * 32 + nt * 8 + ((lane & 3) << 1);
#pragma unroll
            for (int i = 0; i < 4; i++) {
                int r = r0 + ((i >> 1) << 3);
                int cc = c0 + (i & 1);
                if (r < M && cc < N)
                    C[(size_t)r * N + cc] = acc[mt][nt][i] + bias[cc];
            }
        }
}

// ---------------------------------------------------------------------------
// round_copy: dst[i] = tf32(src[i]) — pre-round weights once per launch
// ---------------------------------------------------------------------------
__global__ void round_copy(const float* __restrict__ src, float* __restrict__ dst, int n)
{
    int i = blockIdx.x * 256 + threadIdx.x;
    if (i < n) dst[i] = to_tf32(src[i]);
}

// ---------------------------------------------------------------------------
// LayerNorm (custom eps-outside-sqrt), output rounded to tf32 (feeds GEMMs only)
// ---------------------------------------------------------------------------
__global__ void ln_kernel(const float* __restrict__ in, float* __restrict__ out,
                          const float* __restrict__ w, const float* __restrict__ b,
                          long long istride)
{
    const int r = blockIdx.x, tid = threadIdx.x;
    const float* x = in + (size_t)r * istride;
    float* o = out + (size_t)r * 768;

    float v0 = x[tid], v1 = x[tid + 256], v2 = x[tid + 512];
    float s = v0 + v1 + v2;
    float s2 = v0 * v0 + v1 * v1 + v2 * v2;
#pragma unroll
    for (int ofs = 16; ofs; ofs >>= 1) {
        s  += __shfl_xor_sync(0xffffffffu, s,  ofs);
        s2 += __shfl_xor_sync(0xffffffffu, s2, ofs);
    }
    __shared__ float sa[8], sb[8];
    __shared__ float s_mean, s_rs;
    if ((tid & 31) == 0) { sa[tid >> 5] = s; sb[tid >> 5] = s2; }
    __syncthreads();
    if (tid == 0) {
        float S = 0.f, S2 = 0.f;
#pragma unroll
        for (int i = 0; i < 8; i++) { S += sa[i]; S2 += sb[i]; }
        float mean = S * (1.0f / 768.0f);
        float var  = fmaxf(S2 * (1.0f / 768.0f) - mean * mean, 0.0f);
        s_mean = mean;
        s_rs   = 1.0f / (sqrtf(var) + 1e-5f);
    }
    __syncthreads();
    float mean = s_mean, rs = s_rs;
    o[tid]       = to_tf32((v0 - mean) * rs * w[tid]       + b[tid]);
    o[tid + 256] = to_tf32((v1 - mean) * rs * w[tid + 256] + b[tid + 256]);
    o[tid + 512] = to_tf32((v2 - mean) * rs * w[tid + 512] + b[tid + 512]);
}

// ---------------------------------------------------------------------------
// img_to_patch gather: output rounded (P feeds patch GEMM only)
// ---------------------------------------------------------------------------
__global__ void gather_patches(const float* __restrict__ x, float* __restrict__ p)
{
    int idx = blockIdx.x * 256 + threadIdx.x;
    if (idx >= PROWS * DIM) return;
    int row = idx / 768, kk = idx - row * 768;
    int b = row / 196, pr = row - b * 196;
    int ph = pr / 14, pw = pr - ph * 14;
    int c = kk >> 8, r2 = kk & 255, py = r2 >> 4, px = r2 & 15;
    size_t src = ((size_t)(b * 3 + c) * 224 + (ph * 16 + py)) * 224 + (pw * 16 + px);
    p[idx] = to_tf32(x[src]);
}

__global__ void assemble_h(const float* __restrict__ emb, const float* __restrict__ cls,
                           const float* __restrict__ pos, float* __restrict__ h)
{
    int idx = blockIdx.x * 256 + threadIdx.x;
    if (idx >= ROWS * DIM) return;
    int row = idx / 768, d = idx - row * 768;
    int b = row / 197, s = row - b * 197;
    float v = (s == 0) ? cls[d] : emb[((size_t)b * 196 + (s - 1)) * 768 + d];
    h[idx] = v + pos[s * 768 + d];
}

// ---------------------------------------------------------------------------
// Fused attention (R9 baseline); Yb output rounded (feeds out-proj GEMM only)
// ---------------------------------------------------------------------------
__global__ __launch_bounds__(256, 1)
void attn_kernel(const float* __restrict__ Q, const float* __restrict__ K,
                 const float* __restrict__ V, float* __restrict__ Y)
{
    extern __shared__ float sm[];
    float* Ks = sm;
    float* Vs = Ks + 197 * 65;
    float* Ps = Vs + 197 * 65;

    const int h = blockIdx.x, b = blockIdx.y;
    const int tid = threadIdx.x, wid = tid >> 5, lane = tid & 31;
    const size_t base = (size_t)b * 197 * 768 + h * 64;

    for (int i = tid; i < 197 * 64; i += 256) {
        int s = i >> 6, d = i & 63;
        Ks[s * 65 + d] = K[base + (size_t)s * 768 + d];
        Vs[s * 65 + d] = V[base + (size_t)s * 768 + d];
    }
    __syncthreads();

    for (int g = wid; g < 50; g += 8) {
        int q0 = g * 4;
        int nq = min(4, 197 - q0);
        float qr[4][2];
#pragma unroll
        for (int qi = 0; qi < 4; qi++) {
            if (qi < nq) {
                const float* qp = Q + base + (size_t)(q0 + qi) * 768;
                qr[qi][0] = qp[lane];
                qr[qi][1] = qp[lane + 32];
            } else {
                qr[qi][0] = 0.f; qr[qi][1] = 0.f;
            }
        }
        float* Pw = Ps + (wid * 4) * 200;

#pragma unroll 1
        for (int c = 0; c < 7; c++) {
            int j = c * 32 + lane;
            int jc = (j < 197) ? j : 196;
            const float* kp = Ks + jc * 65;
            float a0 = 0.f, a1 = 0.f, a2 = 0.f, a3 = 0.f;
#pragma unroll
            for (int d = 0; d < 64; d++) {
                float kd = kp[d];
                float q0v = __shfl_sync(0xffffffffu, qr[0][d >> 5], d & 31);
                float q1v = __shfl_sync(0xffffffffu, qr[1][d >> 5], d & 31);
                float q2v = __shfl_sync(0xffffffffu, qr[2][d >> 5], d & 31);
                float q3v = __shfl_sync(0xffffffffu, qr[3][d >> 5], d & 31);
                a0 = fmaf(q0v, kd, a0);
                a1 = fmaf(q1v, kd, a1);
                a2 = fmaf(q2v, kd, a2);
                a3 = fmaf(q3v, kd, a3);
            }
            if (j < 197) {
                Pw[0 * 200 + j] = a0 * 0.125f;
                Pw[1 * 200 + j] = a1 * 0.125f;
                Pw[2 * 200 + j] = a2 * 0.125f;
                Pw[3 * 200 + j] = a3 * 0.125f;
            }
        }
        __syncwarp();

        float inv[4];
#pragma unroll
        for (int qi = 0; qi < 4; qi++) {
            float m = -1e30f;
            for (int j = lane; j < 197; j += 32) m = fmaxf(m, Pw[qi * 200 + j]);
#pragma unroll
            for (int o = 16; o; o >>= 1) m = fmaxf(m, __shfl_xor_sync(0xffffffffu, m, o));
            float ssum = 0.f;
            for (int j = lane; j < 197; j += 32) {
                float e = __expf(Pw[qi * 200 + j] - m);
                Pw[qi * 200 + j] = e;
                ssum += e;
            }
#pragma unroll
            for (int o = 16; o; o >>= 1) ssum += __shfl_xor_sync(0xffffffffu, ssum, o);
            inv[qi] = 1.0f / ssum;
        }
        __syncwarp();

        float o0[4] = {0.f, 0.f, 0.f, 0.f};
        float o1[4] = {0.f, 0.f, 0.f, 0.f};
#pragma unroll 1
        for (int j = 0; j < 197; j++) {
            float v0 = Vs[j * 65 + lane];
            float v1 = Vs[j * 65 + 32 + lane];
#pragma unroll
            for (int qi = 0; qi < 4; qi++) {
                float p = Pw[qi * 200 + j];
                o0[qi] = fmaf(p, v0, o0[qi]);
                o1[qi] = fmaf(p, v1, o1[qi]);
            }
        }
        for (int qi = 0; qi < nq; qi++) {
            float* yp = Y + base + (size_t)(q0 + qi) * 768;
            yp[lane]      = to_tf32(o0[qi] * inv[qi]);
            yp[lane + 32] = to_tf32(o1[qi] * inv[qi]);
        }
        __syncwarp();
    }
}

// ---------------------------------------------------------------------------
// driver
// ---------------------------------------------------------------------------
extern "C" void kernel_launch(void* const* d_in, const int* in_sizes, int n_in,
                              void* d_out, int out_size)
{
    const float* x       = (const float*)d_in[0];
    const float* patch_w = (const float*)d_in[1];
    const float* patch_b = (const float*)d_in[2];
    const float* cls_t   = (const float*)d_in[3];
    const float* pos     = (const float*)d_in[4];
    const float* ln1w    = (const float*)d_in[5];
    const float* ln1b    = (const float*)d_in[6];
    const float* wq      = (const float*)d_in[7];
    const float* bq      = (const float*)d_in[8];
    const float* wk      = (const float*)d_in[9];
    const float* bk      = (const float*)d_in[10];
    const float* wv      = (const float*)d_in[11];
    const float* bv      = (const float*)d_in[12];
    const float* wy      = (const float*)d_in[13];
    const float* by      = (const float*)d_in[14];
    const float* ln2w    = (const float*)d_in[15];
    const float* ln2b    = (const float*)d_in[16];
    const float* m1w     = (const float*)d_in[17];
    const float* m1b     = (const float*)d_in[18];
    const float* m2w     = (const float*)d_in[19];
    const float* m2b     = (const float*)d_in[20];
    const float* hlnw    = (const float*)d_in[21];
    const float* hlnb    = (const float*)d_in[22];
    const float* hw      = (const float*)d_in[23];
    const float* hb      = (const float*)d_in[24];
    float* out = (float*)d_out;

    void* sp = nullptr;
    cudaGetSymbolAddress(&sp, g_scratch);
    float* base = (float*)sp;
    float* P   = base;
    float* H   = P + S_PATCH;
    float* Z   = H + S_ACT;
    float* Qb  = Z + S_ACT;
    float* Kb  = Qb + S_ACT;
    float* Vb  = Kb + S_ACT;
    float* Yb  = Vb + S_ACT;
    float* MB  = Yb + S_ACT;
    float* CLS = MB + S_MLP;
    float* PW  = CLS + S_CLS;          // pre-rounded weights
    float* WQ  = PW + S_PW;
    float* WK  = WQ + S_WX;
    float* WV  = WK + S_WX;
    float* WY  = WV + S_WX;
    float* M1W = WY + S_WX;
    float* M2W = M1W + S_M1;

    cudaFuncSetAttribute(attn_kernel, cudaFuncAttributeMaxDynamicSharedMemorySize, ATTN_SMEM);
    cudaFuncSetAttribute(gemm_old, cudaFuncAttributeMaxDynamicSharedMemorySize, GEMM_SMEM_OLD);
    cudaFuncSetAttribute(gemm_cp<0>, cudaFuncAttributeMaxDynamicSharedMemorySize, CP_SMEM);
    cudaFuncSetAttribute(gemm_cp<1>, cudaFuncAttributeMaxDynamicSharedMemorySize, CP_SMEM);
    cudaFuncSetAttribute(gemm_cp<2>, cudaFuncAttributeMaxDynamicSharedMemorySize, CP_SMEM);

    // Pre-round all GEMM weights to tf32 (deterministic, every launch)
    auto rc = [](const float* s, float* d, size_t n) {
        round_copy<<<(int)((n + 255) / 256), 256>>>(s, d, (int)n);
    };
    rc(patch_w, PW, S_PW);
    rc(wq, WQ, S_WX); rc(wk, WK, S_WX); rc(wv, WV, S_WX); rc(wy, WY, S_WX);
    rc(m1w, M1W, S_M1); rc(m2w, M2W, S_M2);

    // patch embed
    gather_patches<<<(PROWS * DIM + 255) / 256, 256>>>(x, P);
    gemm_cp<0><<<dim3(6, 49), 256, CP_SMEM>>>(P, PW, patch_b, nullptr, Z, PROWS, 768, 768);
    assemble_h<<<(ROWS * DIM + 255) / 256, 256>>>(Z, cls_t, pos, H);

    const dim3 gp(6, 50);     // N=768 GEMMs over 6304 rows
    const dim3 gm1(24, 50);   // N=3072
    for (int l = 0; l < LAYERS; l++) {
        const size_t wo = (size_t)l * 768 * 768;
        const size_t mo = (size_t)l * 768 * 3072;
        ln_kernel<<<ROWS, 256>>>(H, Z, ln1w + l * 768, ln1b + l * 768, 768);
        gemm_cp<0><<<gp, 256, CP_SMEM>>>(Z, WQ + wo, bq + l * 768, nullptr, Qb, ROWS, 768, 768);
        gemm_cp<0><<<gp, 256, CP_SMEM>>>(Z, WK + wo, bk + l * 768, nullptr, Kb, ROWS, 768, 768);
        gemm_cp<0><<<gp, 256, CP_SMEM>>>(Z, WV + wo, bv + l * 768, nullptr, Vb, ROWS, 768, 768);
        attn_kernel<<<dim3(12, 32), 256, ATTN_SMEM>>>(Qb, Kb, Vb, Yb);
        gemm_cp<1><<<gp, 256, CP_SMEM>>>(Yb, WY + wo, by + l * 768, H, H, ROWS, 768, 768);
        ln_kernel<<<ROWS, 256>>>(H, Z, ln2w + l * 768, ln2b + l * 768, 768);
        gemm_cp<2><<<gm1, 256, CP_SMEM>>>(Z, M1W + mo, m1b + (size_t)l * 3072, nullptr, MB, ROWS, 3072, 768);
        gemm_cp<1><<<gp, 256, CP_SMEM>>>(MB, M2W + mo, m2b + l * 768, H, H, ROWS, 768, 3072);
    }

    // head: LN over CLS rows, then [32,768]@[768,1000] (old gemm: N-tail + cvt)
    ln_kernel<<<32, 256>>>(H, CLS, hlnw, hlnb, (long long)197 * 768);
    gemm_old<<<dim3(8, 1), 256, GEMM_SMEM_OLD>>>(CLS, hw, hb, out, 32, NCLS, 768);
}

// round 13
// speedup vs baseline: 1.5766x; 1.2437x over previous
#include <cuda_runtime.h>
#include <cuda_fp16.h>
#include <stdint.h>
#include <math.h>

// ---------------------------------------------------------------------------
// ViT-Base forward: B=32, S=197, D=768, FF=3072, L=12, heads 12x64, out [32,1000]
// GEMMs: fp16 mma.sync (m16n8k16, fp32 accumulate) + 3-stage cp.async pipeline.
// fp16 and tf32 share a 10-bit mantissa: operands pre-rounded to fp16 give the
// same rounding as the R11 tf32 path for these O(1) values -> rel_err ~8.6e-4.
// Weights are pre-transposed+rounded to fp16 [N][K] once per launch.
// Attention math fp32, Q/K/V buffers fp32 (unchanged from R11).
// ---------------------------------------------------------------------------

static constexpr int BATCH = 32, SEQ = 197, DIM = 768, FFD = 3072, LAYERS = 12;
static constexpr int NP = 196, NCLS = 1000;
static constexpr int ROWS  = BATCH * SEQ;   // 6304
static constexpr int PROWS = BATCH * NP;    // 6272

static constexpr size_t S_ACT = (size_t)ROWS * DIM;
static constexpr size_t S_CLS = (size_t)32 * DIM;

// fp32 scratch: Zf (patch-gemm out) + H + Qb + Kb + Vb + CLS
__device__ float g_scratch[5 * S_ACT + S_CLS];

// fp16 scratch: P, Z16, Yb16, MB16 + transposed fp16 weights
static constexpr size_t S_P16 = (size_t)PROWS * DIM;
static constexpr size_t S_Z16 = S_ACT;
static constexpr size_t S_MB  = (size_t)ROWS * FFD;
static constexpr size_t S_PWT = (size_t)768 * 768;
static constexpr size_t S_WXT = (size_t)LAYERS * 768 * 768;
static constexpr size_t S_M1T = (size_t)LAYERS * 768 * 3072;
__device__ __half g_hscratch[S_P16 + 2 * S_Z16 + S_MB + S_PWT + 4 * S_WXT + 2 * S_M1T];

// Attention dynamic smem
static constexpr int ATTN_SMEM_FLOATS = 2 * 197 * 65 + 8 * 4 * 200;
static constexpr int ATTN_SMEM = ATTN_SMEM_FLOATS * 4;  // 128040 B

// Head GEMM (register-staged tf32, unchanged)
static constexpr int AS_SZ = 128 * 36;
static constexpr int BS_SZ = 32 * 136;
static constexpr int GEMM_SMEM_OLD = 2 * (AS_SZ + BS_SZ) * 4;

// fp16 cp.async GEMM: stage = A[128][40]h (10240B) + B[128][40]h (10240B)
static constexpr int CPH_A_BYTES = 128 * 40 * 2;            // 10240
static constexpr int CPH_STAGE   = 2 * CPH_A_BYTES;         // 20480
static constexpr int CPH_SMEM    = 3 * CPH_STAGE;           // 61440

// ---------------------------------------------------------------------------
// helpers
// ---------------------------------------------------------------------------
__device__ __forceinline__ float to_tf32(float x) {
    unsigned u;
    asm("cvt.rna.tf32.f32 %0, %1;" : "=r"(u) : "f"(x));
    return __uint_as_float(u);
}

__device__ __forceinline__ uint32_t smem_u32(const void* p) {
    uint32_t a;
    asm("{ .reg .u64 t; cvta.to.shared.u64 t, %1; cvt.u32.u64 %0, t; }" : "=r"(a) : "l"(p));
    return a;
}

__device__ __forceinline__ void mma_16n8k8(float c[4], const unsigned a[4], const unsigned b[2]) {
    asm volatile(
        "mma.sync.aligned.m16n8k8.row.col.f32.tf32.tf32.f32 "
        "{%0,%1,%2,%3}, {%4,%5,%6,%7}, {%8,%9}, {%0,%1,%2,%3};\n"
        : "+f"(c[0]), "+f"(c[1]), "+f"(c[2]), "+f"(c[3])
        : "r"(a[0]), "r"(a[1]), "r"(a[2]), "r"(a[3]), "r"(b[0]), "r"(b[1]));
}

__device__ __forceinline__ void mma_f16(float c[4], const unsigned a[4], const unsigned b[2]) {
    asm volatile(
        "mma.sync.aligned.m16n8k16.row.col.f32.f16.f16.f32 "
        "{%0,%1,%2,%3}, {%4,%5,%6,%7}, {%8,%9}, {%0,%1,%2,%3};\n"
        : "+f"(c[0]), "+f"(c[1]), "+f"(c[2]), "+f"(c[3])
        : "r"(a[0]), "r"(a[1]), "r"(a[2]), "r"(a[3]), "r"(b[0]), "r"(b[1]));
}

__device__ __forceinline__ void cp16(uint32_t dst, const void* src, bool pred) {
    int sz = pred ? 16 : 0;
    asm volatile("cp.async.cg.shared.global [%0], [%1], 16, %2;\n"
                 :: "r"(dst), "l"(src), "r"(sz) : "memory");
}
#define CP_COMMIT() asm volatile("cp.async.commit_group;" ::: "memory")
#define CP_WAIT1()  asm volatile("cp.async.wait_group 1;" ::: "memory")

__device__ __forceinline__ void store_out(float* C, size_t i, float v)  { C[i] = v; }
__device__ __forceinline__ void store_out(__half* C, size_t i, float v) { C[i] = __float2half_rn(v); }

// ---------------------------------------------------------------------------
// fp16 cp.async GEMM: C[M,N] = A[M,K] @ B[K,N] + bias (+residual | +GELU)
// A fp16 [M][K]; BT fp16 [N][K] (pre-transposed). N%128==0, K%32==0.
// 256 threads, warp grid 2(M)x4(N), warp tile 64x32, k-tile 32 (2x K16 mma).
// EPI: 0 = bias, 1 = bias + residual R (fp32), 2 = bias + exact GELU
// ---------------------------------------------------------------------------
template <int EPI, typename OutT>
__global__ __launch_bounds__(256, 2)
void gemm_cp(const __half* __restrict__ A, const __half* __restrict__ BT,
             const float* __restrict__ bias, const float* R,
             OutT* C, int M, int N, int K)
{
    extern __shared__ float dsm[];
    const uint32_t sbase = smem_u32(dsm);
    const int tid = threadIdx.x, lane = tid & 31, wid = tid >> 5;
    const int wm = wid >> 2, wn = wid & 3;
    const int bm = blockIdx.y << 7, bn = blockIdx.x << 7;

    // One stage: A tile 128 rows x 32 halves, B tile 128 n-rows x 32 halves.
    // 512 + 512 16B-chunks over 256 threads -> 4 cp.async each.
    auto issue = [&](int kt, int slot) {
        const int k0 = kt << 5;
        const uint32_t sa = sbase + slot * CPH_STAGE;
#pragma unroll
        for (int i = 0; i < 2; i++) {
            int c = tid + (i << 8);
            int row = c >> 2, kc = c & 3;
            int gr = bm + row;
            cp16(sa + row * 80 + kc * 16,
                 A + (size_t)gr * K + k0 + kc * 8, gr < M);
        }
#pragma unroll
        for (int i = 0; i < 2; i++) {
            int c = tid + (i << 8);
            int n = c >> 2, kc = c & 3;
            cp16(sa + CPH_A_BYTES + n * 80 + kc * 16,
                 BT + (size_t)(bn + n) * K + k0 + kc * 8, true);
        }
        CP_COMMIT();
    };

    float acc[4][4][4];
#pragma unroll
    for (int mt = 0; mt < 4; mt++)
#pragma unroll
        for (int nt = 0; nt < 4; nt++)
#pragma unroll
            for (int i = 0; i < 4; i++) acc[mt][nt][i] = 0.f;

    const int KT = K >> 5;
    issue(0, 0);
    issue(1, 1);

    for (int kt = 0; kt < KT; kt++) {
        CP_WAIT1();
        __syncthreads();
        const int slot = kt % 3;
        // 32-bit word views; row stride 40 halves = 20 words
        const unsigned* Aw = reinterpret_cast<const unsigned*>(
            reinterpret_cast<const char*>(dsm) + slot * CPH_STAGE);
        const unsigned* Bw = Aw + (CPH_A_BYTES / 4);
#pragma unroll
        for (int ks = 0; ks < 2; ks++) {
            const int kw = ks << 3;              // k offset in words (16 halves)
            unsigned af[4][4], bf[4][2];
#pragma unroll
            for (int mt = 0; mt < 4; mt++) {
                const unsigned* ap = Aw + (wm * 64 + mt * 16 + (lane >> 2)) * 20 + kw + (lane & 3);
                af[mt][0] = ap[0];
                af[mt][1] = ap[8 * 20];
                af[mt][2] = ap[4];
                af[mt][3] = ap[8 * 20 + 4];
            }
#pragma unroll
            for (int nt = 0; nt < 4; nt++) {
                const unsigned* bp = Bw + (wn * 32 + nt * 8 + (lane >> 2)) * 20 + kw + (lane & 3);
                bf[nt][0] = bp[0];
                bf[nt][1] = bp[4];
            }
#pragma unroll
            for (int mt = 0; mt < 4; mt++)
#pragma unroll
                for (int nt = 0; nt < 4; nt++)
                    mma_f16(acc[mt][nt], af[mt], bf[nt]);
        }
        if (kt + 2 < KT) issue(kt + 2, (kt + 2) % 3);
        else             CP_COMMIT();            // empty group keeps wait math
    }

    // epilogue
#pragma unroll
    for (int mt = 0; mt < 4; mt++) {
#pragma unroll
        for (int nt = 0; nt < 4; nt++) {
            int r0 = bm + wm * 64 + mt * 16 + (lane >> 2);
            int c0 = bn + wn * 32 + nt * 8 + ((lane & 3) << 1);
#pragma unroll
            for (int i = 0; i < 4; i++) {
                int r = r0 + ((i >> 1) << 3);
                int cc = c0 + (i & 1);
                if (r < M) {
                    float v = acc[mt][nt][i] + bias[cc];
                    if (EPI == 1) v += R[(size_t)r * N + cc];
                    if (EPI == 2) v = 0.5f * v * (1.0f + erff(v * 0.70710678118654752f));
                    store_out(C, (size_t)r * N + cc, v);
                }
            }
        }
    }
}

// ---------------------------------------------------------------------------
// transpose+round: dst fp16 [C][R] = src fp32 [R][C], batched over grid.z
// block 32x8, tile 32x32 via smem
// ---------------------------------------------------------------------------
__global__ void transpose_w(const float* __restrict__ src, __half* __restrict__ dst,
                            int Rr, int Cc, long long lsrc, long long ldst)
{
    __shared__ float t[32][33];
    const float* s = src + (size_t)blockIdx.z * lsrc;
    __half* d = dst + (size_t)blockIdx.z * ldst;
    int c0 = blockIdx.x * 32, r0 = blockIdx.y * 32;
    int tx = threadIdx.x, ty = threadIdx.y;
#pragma unroll
    for (int j = 0; j < 32; j += 8)
        t[ty + j][tx] = s[(size_t)(r0 + ty + j) * Cc + c0 + tx];
    __syncthreads();
#pragma unroll
    for (int j = 0; j < 32; j += 8)
        d[(size_t)(c0 + ty + j) * Rr + r0 + tx] = __float2half_rn(t[tx][ty + j]);
}

// ---------------------------------------------------------------------------
// Head GEMM (register-staged tf32, N=1000 tail; unchanged from R11)
// ---------------------------------------------------------------------------
__global__ __launch_bounds__(256, 1)
void gemm_old(const float* __restrict__ A, const float* __restrict__ B,
              const float* __restrict__ bias, float* C, int M, int N, int K)
{
    extern __shared__ float dsm2[];
    float* Asb = dsm2;
    float* Bsb = dsm2 + 2 * AS_SZ;

    const int tid = threadIdx.x, lane = tid & 31, wid = tid >> 5;
    const int wm = wid >> 2, wn = wid & 3;
    const int bm = blockIdx.y << 7, bn = blockIdx.x << 7;
    const int ar = tid >> 3, ac = (tid & 7) << 2;
    const int bkr = tid >> 5, bc = (tid & 31) << 2;

    float4 ra[4], rb[4];

    auto gload = [&](int kt) {
        const int k0 = kt << 5;
#pragma unroll
        for (int p = 0; p < 4; p++) {
            int gr = bm + (p << 5) + ar;
            if (gr < M) ra[p] = *reinterpret_cast<const float4*>(A + (size_t)gr * K + k0 + ac);
            else        ra[p] = make_float4(0.f, 0.f, 0.f, 0.f);
        }
#pragma unroll
        for (int p = 0; p < 4; p++) {
            int gk = k0 + (p << 3) + bkr;
            int gn = bn + bc;
            const float* src = B + (size_t)gk * N + gn;
            if (gn + 3 < N) {
                rb[p] = *reinterpret_cast<const float4*>(src);
            } else {
                float4 v;
                v.x = (gn     < N) ? src[0] : 0.f;
                v.y = (gn + 1 < N) ? src[1] : 0.f;
                v.z = (gn + 2 < N) ? src[2] : 0.f;
                v.w = 0.f;
                rb[p] = v;
            }
        }
    };
    auto sstore = [&](int buf) {
        float* As = Asb + buf * AS_SZ;
        float* Bs = Bsb + buf * BS_SZ;
#pragma unroll
        for (int p = 0; p < 4; p++) {
            float4 v = ra[p];
            v.x = to_tf32(v.x); v.y = to_tf32(v.y); v.z = to_tf32(v.z); v.w = to_tf32(v.w);
            *reinterpret_cast<float4*>(&As[((p << 5) + ar) * 36 + ac]) = v;
        }
#pragma unroll
        for (int p = 0; p < 4; p++) {
            float4 v = rb[p];
            v.x = to_tf32(v.x); v.y = to_tf32(v.y); v.z = to_tf32(v.z); v.w = to_tf32(v.w);
            *reinterpret_cast<float4*>(&Bs[((p << 3) + bkr) * 136 + bc]) = v;
        }
    };

    float acc[4][4][4];
#pragma unroll
    for (int mt = 0; mt < 4; mt++)
#pragma unroll
        for (int nt = 0; nt < 4; nt++)
#pragma unroll
            for (int i = 0; i < 4; i++) acc[mt][nt][i] = 0.f;

    gload(0); sstore(0); __syncthreads();
    const int KT = K >> 5;
    for (int kt = 0; kt < KT; kt++) {
        const int buf = kt & 1;
        if (kt + 1 < KT) gload(kt + 1);
        const float* As = Asb + buf * AS_SZ;
        const float* Bs = Bsb + buf * BS_SZ;
#pragma unroll
        for (int ks = 0; ks < 4; ks++) {
            const int ko = ks << 3;
            unsigned af[4][4], bf[4][2];
#pragma unroll
            for (int mt = 0; mt < 4; mt++) {
                const float* ap = &As[(wm * 64 + mt * 16 + (lane >> 2)) * 36 + ko + (lane & 3)];
                af[mt][0] = __float_as_uint(ap[0]);
                af[mt][1] = __float_as_uint(ap[8 * 36]);
                af[mt][2] = __float_as_uint(ap[4]);
                af[mt][3] = __float_as_uint(ap[8 * 36 + 4]);
            }
#pragma unroll
            for (int nt = 0; nt < 4; nt++) {
                const float* bp = &Bs[(ko + (lane & 3)) * 136 + wn * 32 + nt * 8 + (lane >> 2)];
                bf[nt][0] = __float_as_uint(bp[0]);
                bf[nt][1] = __float_as_uint(bp[4 * 136]);
            }
#pragma unroll
            for (int mt = 0; mt < 4; mt++)
#pragma unroll
                for (int nt = 0; nt < 4; nt++)
                    mma_16n8k8(acc[mt][nt], af[mt], bf[nt]);
        }
        if (kt + 1 < KT) sstore(buf ^ 1);
        __syncthreads();
    }
#pragma unroll
    for (int mt = 0; mt < 4; mt++)
#pragma unroll
        for (int nt = 0; nt < 4; nt++) {
            int r0 = bm + wm * 64 + mt * 16 + (lane >> 2);
            int c0 = bn + wn * 32 + nt * 8 + ((lane & 3) << 1);
#pragma unroll
            for (int i = 0; i < 4; i++) {
                int r = r0 + ((i >> 1) << 3);
                int cc = c0 + (i & 1);
                if (r < M && cc < N)
                    C[(size_t)r * N + cc] = acc[mt][nt][i] + bias[cc];
            }
        }
}

// ---------------------------------------------------------------------------
// LayerNorm (custom eps-outside-sqrt); OutT=half for GEMM inputs, float for head
// ---------------------------------------------------------------------------
template <typename OutT>
__global__ void ln_kernel(const float* __restrict__ in, OutT* __restrict__ out,
                          const float* __restrict__ w, const float* __restrict__ b,
                          long long istride)
{
    const int r = blockIdx.x, tid = threadIdx.x;
    const float* x = in + (size_t)r * istride;
    OutT* o = out + (size_t)r * 768;

    float v0 = x[tid], v1 = x[tid + 256], v2 = x[tid + 512];
    float s = v0 + v1 + v2;
    float s2 = v0 * v0 + v1 * v1 + v2 * v2;
#pragma unroll
    for (int ofs = 16; ofs; ofs >>= 1) {
        s  += __shfl_xor_sync(0xffffffffu, s,  ofs);
        s2 += __shfl_xor_sync(0xffffffffu, s2, ofs);
    }
    __shared__ float sa[8], sb[8];
    __shared__ float s_mean, s_rs;
    if ((tid & 31) == 0) { sa[tid >> 5] = s; sb[tid >> 5] = s2; }
    __syncthreads();
    if (tid == 0) {
        float S = 0.f, S2 = 0.f;
#pragma unroll
        for (int i = 0; i < 8; i++) { S += sa[i]; S2 += sb[i]; }
        float mean = S * (1.0f / 768.0f);
        float var  = fmaxf(S2 * (1.0f / 768.0f) - mean * mean, 0.0f);
        s_mean = mean;
        s_rs   = 1.0f / (sqrtf(var) + 1e-5f);
    }
    __syncthreads();
    float mean = s_mean, rs = s_rs;
    store_out(o, (size_t)tid,       (v0 - mean) * rs * w[tid]       + b[tid]);
    store_out(o, (size_t)tid + 256, (v1 - mean) * rs * w[tid + 256] + b[tid + 256]);
    store_out(o, (size_t)tid + 512, (v2 - mean) * rs * w[tid + 512] + b[tid + 512]);
}

// ---------------------------------------------------------------------------
// img_to_patch gather -> fp16 (feeds patch GEMM only)
// ---------------------------------------------------------------------------
__global__ void gather_patches(const float* __restrict__ x, __half* __restrict__ p)
{
    int idx = blockIdx.x * 256 + threadIdx.x;
    if (idx >= PROWS * DIM) return;
    int row = idx / 768, kk = idx - row * 768;
    int b = row / 196, pr = row - b * 196;
    int ph = pr / 14, pw = pr - ph * 14;
    int c = kk >> 8, r2 = kk & 255, py = r2 >> 4, px = r2 & 15;
    size_t src = ((size_t)(b * 3 + c) * 224 + (ph * 16 + py)) * 224 + (pw * 16 + px);
    p[idx] = __float2half_rn(x[src]);
}

__global__ void assemble_h(const float* __restrict__ emb, const float* __restrict__ cls,
                           const float* __restrict__ pos, float* __restrict__ h)
{
    int idx = blockIdx.x * 256 + threadIdx.x;
    if (idx >= ROWS * DIM) return;
    int row = idx / 768, d = idx - row * 768;
    int b = row / 197, s = row - b * 197;
    float v = (s == 0) ? cls[d] : emb[((size_t)b * 196 + (s - 1)) * 768 + d];
    h[idx] = v + pos[s * 768 + d];
}

// ---------------------------------------------------------------------------
// Fused attention: fp32 math, fp32 Q/K/V inputs (unchanged); fp16 Y output
// ---------------------------------------------------------------------------
__global__ __launch_bounds__(256, 1)
void attn_kernel(const float* __restrict__ Q, const float* __restrict__ K,
                 const float* __restrict__ V, __half* __restrict__ Y)
{
    extern __shared__ float sm[];
    float* Ks = sm;
    float* Vs = Ks + 197 * 65;
    float* Ps = Vs + 197 * 65;

    const int h = blockIdx.x, b = blockIdx.y;
    const int tid = threadIdx.x, wid = tid >> 5, lane = tid & 31;
    const size_t base = (size_t)b * 197 * 768 + h * 64;

    for (int i = tid; i < 197 * 64; i += 256) {
        int s = i >> 6, d = i & 63;
        Ks[s * 65 + d] = K[base + (size_t)s * 768 + d];
        Vs[s * 65 + d] = V[base + (size_t)s * 768 + d];
    }
    __syncthreads();

    for (int g = wid; g < 50; g += 8) {
        int q0 = g * 4;
        int nq = min(4, 197 - q0);
        float qr[4][2];
#pragma unroll
        for (int qi = 0; qi < 4; qi++) {
            if (qi < nq) {
                const float* qp = Q + base + (size_t)(q0 + qi) * 768;
                qr[qi][0] = qp[lane];
                qr[qi][1] = qp[lane + 32];
            } else {
                qr[qi][0] = 0.f; qr[qi][1] = 0.f;
            }
        }
        float* Pw = Ps + (wid * 4) * 200;

#pragma unroll 1
        for (int c = 0; c < 7; c++) {
            int j = c * 32 + lane;
            int jc = (j < 197) ? j : 196;
            const float* kp = Ks + jc * 65;
            float a0 = 0.f, a1 = 0.f, a2 = 0.f, a3 = 0.f;
#pragma unroll
            for (int d = 0; d < 64; d++) {
                float kd = kp[d];
                float q0v = __shfl_sync(0xffffffffu, qr[0][d >> 5], d & 31);
                float q1v = __shfl_sync(0xffffffffu, qr[1][d >> 5], d & 31);
                float q2v = __shfl_sync(0xffffffffu, qr[2][d >> 5], d & 31);
                float q3v = __shfl_sync(0xffffffffu, qr[3][d >> 5], d & 31);
                a0 = fmaf(q0v, kd, a0);
                a1 = fmaf(q1v, kd, a1);
                a2 = fmaf(q2v, kd, a2);
                a3 = fmaf(q3v, kd, a3);
            }
            if (j < 197) {
                Pw[0 * 200 + j] = a0 * 0.125f;
                Pw[1 * 200 + j] = a1 * 0.125f;
                Pw[2 * 200 + j] = a2 * 0.125f;
                Pw[3 * 200 + j] = a3 * 0.125f;
            }
        }
        __syncwarp();

        float inv[4];
#pragma unroll
        for (int qi = 0; qi < 4; qi++) {
            float m = -1e30f;
            for (int j = lane; j < 197; j += 32) m = fmaxf(m, Pw[qi * 200 + j]);
#pragma unroll
            for (int o = 16; o; o >>= 1) m = fmaxf(m, __shfl_xor_sync(0xffffffffu, m, o));
            float ssum = 0.f;
            for (int j = lane; j < 197; j += 32) {
                float e = __expf(Pw[qi * 200 + j] - m);
                Pw[qi * 200 + j] = e;
                ssum += e;
            }
#pragma unroll
            for (int o = 16; o; o >>= 1) ssum += __shfl_xor_sync(0xffffffffu, ssum, o);
            inv[qi] = 1.0f / ssum;
        }
        __syncwarp();

        float o0[4] = {0.f, 0.f, 0.f, 0.f};
        float o1[4] = {0.f, 0.f, 0.f, 0.f};
#pragma unroll 1
        for (int j = 0; j < 197; j++) {
            float v0 = Vs[j * 65 + lane];
            float v1 = Vs[j * 65 + 32 + lane];
#pragma unroll
            for (int qi = 0; qi < 4; qi++) {
                float p = Pw[qi * 200 + j];
                o0[qi] = fmaf(p, v0, o0[qi]);
                o1[qi] = fmaf(p, v1, o1[qi]);
            }
        }
        for (int qi = 0; qi < nq; qi++) {
            __half* yp = Y + base + (size_t)(q0 + qi) * 768;
            yp[lane]      = __float2half_rn(o0[qi] * inv[qi]);
            yp[lane + 32] = __float2half_rn(o1[qi] * inv[qi]);
        }
        __syncwarp();
    }
}

// ---------------------------------------------------------------------------
// driver
// ---------------------------------------------------------------------------
extern "C" void kernel_launch(void* const* d_in, const int* in_sizes, int n_in,
                              void* d_out, int out_size)
{
    const float* x       = (const float*)d_in[0];
    const float* patch_w = (const float*)d_in[1];
    const float* patch_b = (const float*)d_in[2];
    const float* cls_t   = (const float*)d_in[3];
    const float* pos     = (const float*)d_in[4];
    const float* ln1w    = (const float*)d_in[5];
    const float* ln1b    = (const float*)d_in[6];
    const float* wq      = (const float*)d_in[7];
    const float* bq      = (const float*)d_in[8];
    const float* wk      = (const float*)d_in[9];
    const float* bk      = (const float*)d_in[10];
    const float* wv      = (const float*)d_in[11];
    const float* bv      = (const float*)d_in[12];
    const float* wy      = (const float*)d_in[13];
    const float* by      = (const float*)d_in[14];
    const float* ln2w    = (const float*)d_in[15];
    const float* ln2b    = (const float*)d_in[16];
    const float* m1w     = (const float*)d_in[17];
    const float* m1b     = (const float*)d_in[18];
    const float* m2w     = (const float*)d_in[19];
    const float* m2b     = (const float*)d_in[20];
    const float* hlnw    = (const float*)d_in[21];
    const float* hlnb    = (const float*)d_in[22];
    const float* hw      = (const float*)d_in[23];
    const float* hb      = (const float*)d_in[24];
    float* out = (float*)d_out;

    void* sp = nullptr;
    cudaGetSymbolAddress(&sp, g_scratch);
    float* fbase = (float*)sp;
    float* Zf  = fbase;                // patch-gemm out (fp32)
    float* H   = Zf + S_ACT;
    float* Qb  = H + S_ACT;
    float* Kb  = Qb + S_ACT;
    float* Vb  = Kb + S_ACT;
    float* CLS = Vb + S_ACT;

    void* hp = nullptr;
    cudaGetSymbolAddress(&hp, g_hscratch);
    __half* P16  = (__half*)hp;
    __half* Z16  = P16 + S_P16;
    __half* Y16  = Z16 + S_Z16;
    __half* MB16 = Y16 + S_Z16;
    __half* PWT  = MB16 + S_MB;
    __half* WQT  = PWT + S_PWT;
    __half* WKT  = WQT + S_WXT;
    __half* WVT  = WKT + S_WXT;
    __half* WYT  = WVT + S_WXT;
    __half* M1T  = WYT + S_WXT;
    __half* M2T  = M1T + S_M1T;

    cudaFuncSetAttribute(attn_kernel, cudaFuncAttributeMaxDynamicSharedMemorySize, ATTN_SMEM);
    cudaFuncSetAttribute(gemm_old, cudaFuncAttributeMaxDynamicSharedMemorySize, GEMM_SMEM_OLD);
    cudaFuncSetAttribute((const void*)gemm_cp<0, float>,  cudaFuncAttributeMaxDynamicSharedMemorySize, CPH_SMEM);
    cudaFuncSetAttribute((const void*)gemm_cp<1, float>,  cudaFuncAttributeMaxDynamicSharedMemorySize, CPH_SMEM);
    cudaFuncSetAttribute((const void*)gemm_cp<2, __half>, cudaFuncAttributeMaxDynamicSharedMemorySize, CPH_SMEM);

    // Transpose+round all weights to fp16 [N][K] (deterministic, every launch)
    {
        dim3 blk(32, 8);
        transpose_w<<<dim3(24, 24, 1),  blk>>>(patch_w, PWT, 768, 768, 0, 0);
        transpose_w<<<dim3(24, 24, 12), blk>>>(wq, WQT, 768, 768, 768 * 768, 768 * 768);
        transpose_w<<<dim3(24, 24, 12), blk>>>(wk, WKT, 768, 768, 768 * 768, 768 * 768);
        transpose_w<<<dim3(24, 24, 12), blk>>>(wv, WVT, 768, 768, 768 * 768, 768 * 768);
        transpose_w<<<dim3(24, 24, 12), blk>>>(wy, WYT, 768, 768, 768 * 768, 768 * 768);
        transpose_w<<<dim3(96, 24, 12), blk>>>(m1w, M1T, 768, 3072, 768 * 3072, 768 * 3072);
        transpose_w<<<dim3(24, 96, 12), blk>>>(m2w, M2T, 3072, 768, 768 * 3072, 768 * 3072);
    }

    // patch embed
    gather_patches<<<(PROWS * DIM + 255) / 256, 256>>>(x, P16);
    gemm_cp<0, float><<<dim3(6, 49), 256, CPH_SMEM>>>(P16, PWT, patch_b, nullptr, Zf, PROWS, 768, 768);
    assemble_h<<<(ROWS * DIM + 255) / 256, 256>>>(Zf, cls_t, pos, H);

    const dim3 gp(6, 50);     // N=768 GEMMs over 6304 rows
    const dim3 gm1(24, 50);   // N=3072
    for (int l = 0; l < LAYERS; l++) {
        const size_t wo = (size_t)l * 768 * 768;
        const size_t mo = (size_t)l * 768 * 3072;
        ln_kernel<__half><<<ROWS, 256>>>(H, Z16, ln1w + l * 768, ln1b + l * 768, 768);
        gemm_cp<0, float><<<gp, 256, CPH_SMEM>>>(Z16, WQT + wo, bq + l * 768, nullptr, Qb, ROWS, 768, 768);
        gemm_cp<0, float><<<gp, 256, CPH_SMEM>>>(Z16, WKT + wo, bk + l * 768, nullptr, Kb, ROWS, 768, 768);
        gemm_cp<0, float><<<gp, 256, CPH_SMEM>>>(Z16, WVT + wo, bv + l * 768, nullptr, Vb, ROWS, 768, 768);
        attn_kernel<<<dim3(12, 32), 256, ATTN_SMEM>>>(Qb, Kb, Vb, Y16);
        gemm_cp<1, float><<<gp, 256, CPH_SMEM>>>(Y16, WYT + wo, by + l * 768, H, H, ROWS, 768, 768);
        ln_kernel<__half><<<ROWS, 256>>>(H, Z16, ln2w + l * 768, ln2b + l * 768, 768);
        gemm_cp<2, __half><<<gm1, 256, CPH_SMEM>>>(Z16, M1T + mo, m1b + (size_t)l * 3072, nullptr, MB16, ROWS, 3072, 768);
        gemm_cp<1, float><<<gp, 256, CPH_SMEM>>>(MB16, M2T + mo, m2b + l * 768, H, H, ROWS, 768, 3072);
    }

    // head: LN (fp32 out) over CLS rows, then [32,768]@[768,1000]
    ln_kernel<float><<<32, 256>>>(H, CLS, hlnw, hlnb, (long long)197 * 768);
    gemm_old<<<dim3(8, 1), 256, GEMM_SMEM_OLD>>>(CLS, hw, hb, out, 32, NCLS, 768);
}

// round 16
// speedup vs baseline: 1.6641x; 1.0555x over previous
#include <cuda_runtime.h>
#include <cuda_fp16.h>
#include <stdint.h>
#include <math.h>

// ---------------------------------------------------------------------------
// ViT-Base forward: B=32, S=197, D=768, FF=3072, L=12, heads 12x64, out [32,1000]
// GEMMs: fp16 mma.sync m16n8k16 (fp32 accum) + 3-stage cp.async pipeline +
// ldmatrix.x4 fragment loads. QKV projections fused into one N=2304 GEMM.
// Attention math fp32 (row stride parameterized). Weights pre-transposed fp16.
// ---------------------------------------------------------------------------

static constexpr int BATCH = 32, SEQ = 197, DIM = 768, FFD = 3072, LAYERS = 12;
static constexpr int NP = 196, NCLS = 1000;
static constexpr int ROWS  = BATCH * SEQ;   // 6304
static constexpr int PROWS = BATCH * NP;    // 6272

static constexpr size_t S_ACT = (size_t)ROWS * DIM;
static constexpr size_t S_CLS = (size_t)32 * DIM;
static constexpr size_t S_BQ  = (size_t)LAYERS * 2304;

// fp32 scratch: Zf + H + QKV(3*S_ACT) + CLS + fused-bias
__device__ float g_scratch[5 * S_ACT + S_CLS + S_BQ];

// fp16 scratch: P16, Z16, Y16, MB16 + transposed fp16 weights
static constexpr size_t S_P16 = (size_t)PROWS * DIM;
static constexpr size_t S_Z16 = S_ACT;
static constexpr size_t S_MB  = (size_t)ROWS * FFD;
static constexpr size_t S_PWT = (size_t)768 * 768;
static constexpr size_t S_QKV = (size_t)LAYERS * 2304 * 768;   // fused QKV weights
static constexpr size_t S_WXT = (size_t)LAYERS * 768 * 768;    // out-proj
static constexpr size_t S_M1T = (size_t)LAYERS * 768 * 3072;
__device__ __half g_hscratch[S_P16 + 2 * S_Z16 + S_MB + S_PWT + S_QKV + S_WXT + 2 * S_M1T];

// Attention dynamic smem
static constexpr int ATTN_SMEM_FLOATS = 2 * 197 * 65 + 8 * 4 * 200;
static constexpr int ATTN_SMEM = ATTN_SMEM_FLOATS * 4;  // 128040 B

// Head GEMM (register-staged tf32)
static constexpr int AS_SZ = 128 * 36;
static constexpr int BS_SZ = 32 * 136;
static constexpr int GEMM_SMEM_OLD = 2 * (AS_SZ + BS_SZ) * 4;

// fp16 cp.async GEMM: stage = A[128][40]h + B[128][40]h
static constexpr int CPH_A_BYTES = 128 * 40 * 2;            // 10240
static constexpr int CPH_STAGE   = 2 * CPH_A_BYTES;         // 20480
static constexpr int CPH_SMEM    = 3 * CPH_STAGE;           // 61440

// ---------------------------------------------------------------------------
// helpers
// ---------------------------------------------------------------------------
__device__ __forceinline__ float to_tf32(float x) {
    unsigned u;
    asm("cvt.rna.tf32.f32 %0, %1;" : "=r"(u) : "f"(x));
    return __uint_as_float(u);
}

__device__ __forceinline__ uint32_t smem_u32(const void* p) {
    uint32_t a;
    asm("{ .reg .u64 t; cvta.to.shared.u64 t, %1; cvt.u32.u64 %0, t; }" : "=r"(a) : "l"(p));
    return a;
}

__device__ __forceinline__ void mma_16n8k8(float c[4], const unsigned a[4], const unsigned b[2]) {
    asm volatile(
        "mma.sync.aligned.m16n8k8.row.col.f32.tf32.tf32.f32 "
        "{%0,%1,%2,%3}, {%4,%5,%6,%7}, {%8,%9}, {%0,%1,%2,%3};\n"
        : "+f"(c[0]), "+f"(c[1]), "+f"(c[2]), "+f"(c[3])
        : "r"(a[0]), "r"(a[1]), "r"(a[2]), "r"(a[3]), "r"(b[0]), "r"(b[1]));
}

__device__ __forceinline__ void mma_f16(float c[4], const unsigned a[4], const unsigned b[2]) {
    asm volatile(
        "mma.sync.aligned.m16n8k16.row.col.f32.f16.f16.f32 "
        "{%0,%1,%2,%3}, {%4,%5,%6,%7}, {%8,%9}, {%0,%1,%2,%3};\n"
        : "+f"(c[0]), "+f"(c[1]), "+f"(c[2]), "+f"(c[3])
        : "r"(a[0]), "r"(a[1]), "r"(a[2]), "r"(a[3]), "r"(b[0]), "r"(b[1]));
}

__device__ __forceinline__ void ldsm_x4(unsigned r[4], uint32_t addr) {
    asm volatile("ldmatrix.sync.aligned.m8n8.x4.shared.b16 {%0,%1,%2,%3}, [%4];"
                 : "=r"(r[0]), "=r"(r[1]), "=r"(r[2]), "=r"(r[3]) : "r"(addr));
}

__device__ __forceinline__ void cp16(uint32_t dst, const void* src, bool pred) {
    int sz = pred ? 16 : 0;
    asm volatile("cp.async.cg.shared.global [%0], [%1], 16, %2;\n"
                 :: "r"(dst), "l"(src), "r"(sz) : "memory");
}
#define CP_COMMIT() asm volatile("cp.async.commit_group;" ::: "memory")
#define CP_WAIT1()  asm volatile("cp.async.wait_group 1;" ::: "memory")

__device__ __forceinline__ void store_out(float* C, size_t i, float v)  { C[i] = v; }
__device__ __forceinline__ void store_out(__half* C, size_t i, float v) { C[i] = __float2half_rn(v); }

// ---------------------------------------------------------------------------
// fp16 cp.async GEMM: C[M,N] = A[M,K] @ B[K,N] + bias (+residual | +GELU)
// A fp16 [M][K]; BT fp16 [N][K]. N%128==0, K%32==0. ldmatrix fragment loads.
// 256 threads, warp grid 2(M)x4(N), warp tile 64x32, k-tile 32.
// ---------------------------------------------------------------------------
template <int EPI, typename OutT>
__global__ __launch_bounds__(256, 2)
void gemm_cp(const __half* __restrict__ A, const __half* __restrict__ BT,
             const float* __restrict__ bias, const float* R,
             OutT* C, int M, int N, int K)
{
    extern __shared__ float dsm[];
    const uint32_t sbase = smem_u32(dsm);
    const int tid = threadIdx.x, lane = tid & 31, wid = tid >> 5;
    const int wm = wid >> 2, wn = wid & 3;
    const int bm = blockIdx.y << 7, bn = blockIdx.x << 7;

    auto issue = [&](int kt, int slot) {
        const int k0 = kt << 5;
        const uint32_t sa = sbase + slot * CPH_STAGE;
#pragma unroll
        for (int i = 0; i < 2; i++) {
            int c = tid + (i << 8);
            int row = c >> 2, kc = c & 3;
            int gr = bm + row;
            cp16(sa + row * 80 + kc * 16,
                 A + (size_t)gr * K + k0 + kc * 8, gr < M);
        }
#pragma unroll
        for (int i = 0; i < 2; i++) {
            int c = tid + (i << 8);
            int n = c >> 2, kc = c & 3;
            cp16(sa + CPH_A_BYTES + n * 80 + kc * 16,
                 BT + (size_t)(bn + n) * K + k0 + kc * 8, true);
        }
        CP_COMMIT();
    };

    // ldmatrix lane-offsets (bytes, stage-relative)
    const uint32_t aLaneOff = (uint32_t)((wm * 64 + (lane & 15)) * 80 + ((lane >> 4) << 4));
    const uint32_t bLaneOff = (uint32_t)(CPH_A_BYTES + (wn * 32 + (lane & 7)) * 80 + ((lane >> 3) << 4));

    float acc[4][4][4];
#pragma unroll
    for (int mt = 0; mt < 4; mt++)
#pragma unroll
        for (int nt = 0; nt < 4; nt++)
#pragma unroll
            for (int i = 0; i < 4; i++) acc[mt][nt][i] = 0.f;

    const int KT = K >> 5;
    issue(0, 0);
    issue(1, 1);

    for (int kt = 0; kt < KT; kt++) {
        CP_WAIT1();
        __syncthreads();
        const uint32_t sa = sbase + (kt % 3) * CPH_STAGE;

        // B: one x4 per nt covers both k-steps:
        //   r0,r1 = (b0,b1) of ks0 ; r2,r3 = (b0,b1) of ks1
        unsigned bfr[4][4];
#pragma unroll
        for (int nt = 0; nt < 4; nt++)
            ldsm_x4(bfr[nt], sa + bLaneOff + nt * 640);

#pragma unroll
        for (int ks = 0; ks < 2; ks++) {
            unsigned af[4][4];
#pragma unroll
            for (int mt = 0; mt < 4; mt++)
                ldsm_x4(af[mt], sa + aLaneOff + mt * 1280 + ks * 32);
#pragma unroll
            for (int mt = 0; mt < 4; mt++)
#pragma unroll
                for (int nt = 0; nt < 4; nt++)
                    mma_f16(acc[mt][nt], af[mt], &bfr[nt][ks * 2]);
        }
        if (kt + 2 < KT) issue(kt + 2, (kt + 2) % 3);
        else             CP_COMMIT();            // empty group keeps wait math
    }

    // epilogue
#pragma unroll
    for (int mt = 0; mt < 4; mt++) {
#pragma unroll
        for (int nt = 0; nt < 4; nt++) {
            int r0 = bm + wm * 64 + mt * 16 + (lane >> 2);
            int c0 = bn + wn * 32 + nt * 8 + ((lane & 3) << 1);
#pragma unroll
            for (int i = 0; i < 4; i++) {
                int r = r0 + ((i >> 1) << 3);
                int cc = c0 + (i & 1);
                if (r < M) {
                    float v = acc[mt][nt][i] + bias[cc];
                    if (EPI == 1) v += R[(size_t)r * N + cc];
                    if (EPI == 2) v = 0.5f * v * (1.0f + erff(v * 0.70710678118654752f));
                    store_out(C, (size_t)r * N + cc, v);
                }
            }
        }
    }
}

// ---------------------------------------------------------------------------
// transpose+round: dst fp16 [C][R] = src fp32 [R][C], batched over grid.z
// ---------------------------------------------------------------------------
__global__ void transpose_w(const float* __restrict__ src, __half* __restrict__ dst,
                            int Rr, int Cc, long long lsrc, long long ldst)
{
    __shared__ float t[32][33];
    const float* s = src + (size_t)blockIdx.z * lsrc;
    __half* d = dst + (size_t)blockIdx.z * ldst;
    int c0 = blockIdx.x * 32, r0 = blockIdx.y * 32;
    int tx = threadIdx.x, ty = threadIdx.y;
#pragma unroll
    for (int j = 0; j < 32; j += 8)
        t[ty + j][tx] = s[(size_t)(r0 + ty + j) * Cc + c0 + tx];
    __syncthreads();
#pragma unroll
    for (int j = 0; j < 32; j += 8)
        d[(size_t)(c0 + ty + j) * Rr + r0 + tx] = __float2half_rn(t[tx][ty + j]);
}

// concat per-layer QKV bias: out[l][0:768)=bq, [768:1536)=bk, [1536:2304)=bv
__global__ void concat_bias(const float* __restrict__ bq, const float* __restrict__ bk,
                            const float* __restrict__ bv, float* __restrict__ o)
{
    int idx = blockIdx.x * 256 + threadIdx.x;
    if (idx >= LAYERS * 2304) return;
    int l = idx / 2304, n = idx - l * 2304;
    float v = (n < 768) ? bq[l * 768 + n] : (n < 1536) ? bk[l * 768 + n - 768]
                                                       : bv[l * 768 + n - 1536];
    o[idx] = v;
}

// ---------------------------------------------------------------------------
// Head GEMM (register-staged tf32, N=1000 tail)
// ---------------------------------------------------------------------------
__global__ __launch_bounds__(256, 1)
void gemm_old(const float* __restrict__ A, const float* __restrict__ B,
              const float* __restrict__ bias, float* C, int M, int N, int K)
{
    extern __shared__ float dsm2[];
    float* Asb = dsm2;
    float* Bsb = dsm2 + 2 * AS_SZ;

    const int tid = threadIdx.x, lane = tid & 31, wid = tid >> 5;
    const int wm = wid >> 2, wn = wid & 3;
    const int bm = blockIdx.y << 7, bn = blockIdx.x << 7;
    const int ar = tid >> 3, ac = (tid & 7) << 2;
    const int bkr = tid >> 5, bc = (tid & 31) << 2;

    float4 ra[4], rb[4];

    auto gload = [&](int kt) {
        const int k0 = kt << 5;
#pragma unroll
        for (int p = 0; p < 4; p++) {
            int gr = bm + (p << 5) + ar;
            if (gr < M) ra[p] = *reinterpret_cast<const float4*>(A + (size_t)gr * K + k0 + ac);
            else        ra[p] = make_float4(0.f, 0.f, 0.f, 0.f);
        }
#pragma unroll
        for (int p = 0; p < 4; p++) {
            int gk = k0 + (p << 3) + bkr;
            int gn = bn + bc;
            const float* src = B + (size_t)gk * N + gn;
            if (gn + 3 < N) {
                rb[p] = *reinterpret_cast<const float4*>(src);
            } else {
                float4 v;
                v.x = (gn     < N) ? src[0] : 0.f;
                v.y = (gn + 1 < N) ? src[1] : 0.f;
                v.z = (gn + 2 < N) ? src[2] : 0.f;
                v.w = 0.f;
                rb[p] = v;
            }
        }
    };
    auto sstore = [&](int buf) {
        float* As = Asb + buf * AS_SZ;
        float* Bs = Bsb + buf * BS_SZ;
#pragma unroll
        for (int p = 0; p < 4; p++) {
            float4 v = ra[p];
            v.x = to_tf32(v.x); v.y = to_tf32(v.y); v.z = to_tf32(v.z); v.w = to_tf32(v.w);
            *reinterpret_cast<float4*>(&As[((p << 5) + ar) * 36 + ac]) = v;
        }
#pragma unroll
        for (int p = 0; p < 4; p++) {
            float4 v = rb[p];
            v.x = to_tf32(v.x); v.y = to_tf32(v.y); v.z = to_tf32(v.z); v.w = to_tf32(v.w);
            *reinterpret_cast<float4*>(&Bs[((p << 3) + bkr) * 136 + bc]) = v;
        }
    };

    float acc[4][4][4];
#pragma unroll
    for (int mt = 0; mt < 4; mt++)
#pragma unroll
        for (int nt = 0; nt < 4; nt++)
#pragma unroll
            for (int i = 0; i < 4; i++) acc[mt][nt][i] = 0.f;

    gload(0); sstore(0); __syncthreads();
    const int KT = K >> 5;
    for (int kt = 0; kt < KT; kt++) {
        const int buf = kt & 1;
        if (kt + 1 < KT) gload(kt + 1);
        const float* As = Asb + buf * AS_SZ;
        const float* Bs = Bsb + buf * BS_SZ;
#pragma unroll
        for (int ks = 0; ks < 4; ks++) {
            const int ko = ks << 3;
            unsigned af[4][4], bf[4][2];
#pragma unroll
            for (int mt = 0; mt < 4; mt++) {
                const float* ap = &As[(wm * 64 + mt * 16 + (lane >> 2)) * 36 + ko + (lane & 3)];
                af[mt][0] = __float_as_uint(ap[0]);
                af[mt][1] = __float_as_uint(ap[8 * 36]);
                af[mt][2] = __float_as_uint(ap[4]);
                af[mt][3] = __float_as_uint(ap[8 * 36 + 4]);
            }
#pragma unroll
            for (int nt = 0; nt < 4; nt++) {
                const float* bp = &Bs[(ko + (lane & 3)) * 136 + wn * 32 + nt * 8 + (lane >> 2)];
                bf[nt][0] = __float_as_uint(bp[0]);
                bf[nt][1] = __float_as_uint(bp[4 * 136]);
            }
#pragma unroll
            for (int mt = 0; mt < 4; mt++)
#pragma unroll
                for (int nt = 0; nt < 4; nt++)
                    mma_16n8k8(acc[mt][nt], af[mt], bf[nt]);
        }
        if (kt + 1 < KT) sstore(buf ^ 1);
        __syncthreads();
    }
#pragma unroll
    for (int mt = 0; mt < 4; mt++)
#pragma unroll
        for (int nt = 0; nt < 4; nt++) {
            int r0 = bm + wm * 64 + mt * 16 + (lane >> 2);
            int c0 = bn + wn * 32 + nt * 8 + ((lane & 3) << 1);
#pragma unroll
            for (int i = 0; i < 4; i++) {
                int r = r0 + ((i >> 1) << 3);
                int cc = c0 + (i & 1);
                if (r < M && cc < N)
                    C[(size_t)r * N + cc] = acc[mt][nt][i] + bias[cc];
            }
        }
}

// ---------------------------------------------------------------------------
// LayerNorm (custom eps-outside-sqrt)
// ---------------------------------------------------------------------------
template <typename OutT>
__global__ void ln_kernel(const float* __restrict__ in, OutT* __restrict__ out,
                          const float* __restrict__ w, const float* __restrict__ b,
                          long long istride)
{
    const int r = blockIdx.x, tid = threadIdx.x;
    const float* x = in + (size_t)r * istride;
    OutT* o = out + (size_t)r * 768;

    float v0 = x[tid], v1 = x[tid + 256], v2 = x[tid + 512];
    float s = v0 + v1 + v2;
    float s2 = v0 * v0 + v1 * v1 + v2 * v2;
#pragma unroll
    for (int ofs = 16; ofs; ofs >>= 1) {
        s  += __shfl_xor_sync(0xffffffffu, s,  ofs);
        s2 += __shfl_xor_sync(0xffffffffu, s2, ofs);
    }
    __shared__ float sa[8], sb[8];
    __shared__ float s_mean, s_rs;
    if ((tid & 31) == 0) { sa[tid >> 5] = s; sb[tid >> 5] = s2; }
    __syncthreads();
    if (tid == 0) {
        float S = 0.f, S2 = 0.f;
#pragma unroll
        for (int i = 0; i < 8; i++) { S += sa[i]; S2 += sb[i]; }
        float mean = S * (1.0f / 768.0f);
        float var  = fmaxf(S2 * (1.0f / 768.0f) - mean * mean, 0.0f);
        s_mean = mean;
        s_rs   = 1.0f / (sqrtf(var) + 1e-5f);
    }
    __syncthreads();
    float mean = s_mean, rs = s_rs;
    store_out(o, (size_t)tid,       (v0 - mean) * rs * w[tid]       + b[tid]);
    store_out(o, (size_t)tid + 256, (v1 - mean) * rs * w[tid + 256] + b[tid + 256]);
    store_out(o, (size_t)tid + 512, (v2 - mean) * rs * w[tid + 512] + b[tid + 512]);
}

// ---------------------------------------------------------------------------
// img_to_patch gather -> fp16
// ---------------------------------------------------------------------------
__global__ void gather_patches(const float* __restrict__ x, __half* __restrict__ p)
{
    int idx = blockIdx.x * 256 + threadIdx.x;
    if (idx >= PROWS * DIM) return;
    int row = idx / 768, kk = idx - row * 768;
    int b = row / 196, pr = row - b * 196;
    int ph = pr / 14, pw = pr - ph * 14;
    int c = kk >> 8, r2 = kk & 255, py = r2 >> 4, px = r2 & 15;
    size_t src = ((size_t)(b * 3 + c) * 224 + (ph * 16 + py)) * 224 + (pw * 16 + px);
    p[idx] = __float2half_rn(x[src]);
}

__global__ void assemble_h(const float* __restrict__ emb, const float* __restrict__ cls,
                           const float* __restrict__ pos, float* __restrict__ h)
{
    int idx = blockIdx.x * 256 + threadIdx.x;
    if (idx >= ROWS * DIM) return;
    int row = idx / 768, d = idx - row * 768;
    int b = row / 197, s = row - b * 197;
    float v = (s == 0) ? cls[d] : emb[((size_t)b * 196 + (s - 1)) * 768 + d];
    h[idx] = v + pos[s * 768 + d];
}

// ---------------------------------------------------------------------------
// Fused attention: fp32 math; Q/K/V read from fused QKV buffer (row stride lds)
// ---------------------------------------------------------------------------
__global__ __launch_bounds__(256, 1)
void attn_kernel(const float* __restrict__ Q, const float* __restrict__ K,
                 const float* __restrict__ V, __half* __restrict__ Y, int lds)
{
    extern __shared__ float sm[];
    float* Ks = sm;
    float* Vs = Ks + 197 * 65;
    float* Ps = Vs + 197 * 65;

    const int h = blockIdx.x, b = blockIdx.y;
    const int tid = threadIdx.x, wid = tid >> 5, lane = tid & 31;
    const size_t base = (size_t)b * 197 * lds + h * 64;
    const size_t ybase = (size_t)b * 197 * 768 + h * 64;

    for (int i = tid; i < 197 * 64; i += 256) {
        int s = i >> 6, d = i & 63;
        Ks[s * 65 + d] = K[base + (size_t)s * lds + d];
        Vs[s * 65 + d] = V[base + (size_t)s * lds + d];
    }
    __syncthreads();

    for (int g = wid; g < 50; g += 8) {
        int q0 = g * 4;
        int nq = min(4, 197 - q0);
        float qr[4][2];
#pragma unroll
        for (int qi = 0; qi < 4; qi++) {
            if (qi < nq) {
                const float* qp = Q + base + (size_t)(q0 + qi) * lds;
                qr[qi][0] = qp[lane];
                qr[qi][1] = qp[lane + 32];
            } else {
                qr[qi][0] = 0.f; qr[qi][1] = 0.f;
            }
        }
        float* Pw = Ps + (wid * 4) * 200;

#pragma unroll 1
        for (int c = 0; c < 7; c++) {
            int j = c * 32 + lane;
            int jc = (j < 197) ? j : 196;
            const float* kp = Ks + jc * 65;
            float a0 = 0.f, a1 = 0.f, a2 = 0.f, a3 = 0.f;
#pragma unroll
            for (int d = 0; d < 64; d++) {
                float kd = kp[d];
                float q0v = __shfl_sync(0xffffffffu, qr[0][d >> 5], d & 31);
                float q1v = __shfl_sync(0xffffffffu, qr[1][d >> 5], d & 31);
                float q2v = __shfl_sync(0xffffffffu, qr[2][d >> 5], d & 31);
                float q3v = __shfl_sync(0xffffffffu, qr[3][d >> 5], d & 31);
                a0 = fmaf(q0v, kd, a0);
                a1 = fmaf(q1v, kd, a1);
                a2 = fmaf(q2v, kd, a2);
                a3 = fmaf(q3v, kd, a3);
            }
            if (j < 197) {
                Pw[0 * 200 + j] = a0 * 0.125f;
                Pw[1 * 200 + j] = a1 * 0.125f;
                Pw[2 * 200 + j] = a2 * 0.125f;
                Pw[3 * 200 + j] = a3 * 0.125f;
            }
        }
        __syncwarp();

        float inv[4];
#pragma unroll
        for (int qi = 0; qi < 4; qi++) {
            float m = -1e30f;
            for (int j = lane; j < 197; j += 32) m = fmaxf(m, Pw[qi * 200 + j]);
#pragma unroll
            for (int o = 16; o; o >>= 1) m = fmaxf(m, __shfl_xor_sync(0xffffffffu, m, o));
            float ssum = 0.f;
            for (int j = lane; j < 197; j += 32) {
                float e = __expf(Pw[qi * 200 + j] - m);
                Pw[qi * 200 + j] = e;
                ssum += e;
            }
#pragma unroll
            for (int o = 16; o; o >>= 1) ssum += __shfl_xor_sync(0xffffffffu, ssum, o);
            inv[qi] = 1.0f / ssum;
        }
        __syncwarp();

        float o0[4] = {0.f, 0.f, 0.f, 0.f};
        float o1[4] = {0.f, 0.f, 0.f, 0.f};
#pragma unroll 1
        for (int j = 0; j < 197; j++) {
            float v0 = Vs[j * 65 + lane];
            float v1 = Vs[j * 65 + 32 + lane];
#pragma unroll
            for (int qi = 0; qi < 4; qi++) {
                float p = Pw[qi * 200 + j];
                o0[qi] = fmaf(p, v0, o0[qi]);
                o1[qi] = fmaf(p, v1, o1[qi]);
            }
        }
        for (int qi = 0; qi < nq; qi++) {
            __half* yp = Y + ybase + (size_t)(q0 + qi) * 768;
            yp[lane]      = __float2half_rn(o0[qi] * inv[qi]);
            yp[lane + 32] = __float2half_rn(o1[qi] * inv[qi]);
        }
        __syncwarp();
    }
}

// ---------------------------------------------------------------------------
// driver
// ---------------------------------------------------------------------------
extern "C" void kernel_launch(void* const* d_in, const int* in_sizes, int n_in,
                              void* d_out, int out_size)
{
    const float* x       = (const float*)d_in[0];
    const float* patch_w = (const float*)d_in[1];
    const float* patch_b = (const float*)d_in[2];
    const float* cls_t   = (const float*)d_in[3];
    const float* pos     = (const float*)d_in[4];
    const float* ln1w    = (const float*)d_in[5];
    const float* ln1b    = (const float*)d_in[6];
    const float* wq      = (const float*)d_in[7];
    const float* bq      = (const float*)d_in[8];
    const float* wk      = (const float*)d_in[9];
    const float* bk      = (const float*)d_in[10];
    const float* wv      = (const float*)d_in[11];
    const float* bv      = (const float*)d_in[12];
    const float* wy      = (const float*)d_in[13];
    const float* by      = (const float*)d_in[14];
    const float* ln2w    = (const float*)d_in[15];
    const float* ln2b    = (const float*)d_in[16];
    const float* m1w     = (const float*)d_in[17];
    const float* m1b     = (const float*)d_in[18];
    const float* m2w     = (const float*)d_in[19];
    const float* m2b     = (const float*)d_in[20];
    const float* hlnw    = (const float*)d_in[21];
    const float* hlnb    = (const float*)d_in[22];
    const float* hw      = (const float*)d_in[23];
    const float* hb      = (const float*)d_in[24];
    float* out = (float*)d_out;

    void* sp = nullptr;
    cudaGetSymbolAddress(&sp, g_scratch);
    float* fbase = (float*)sp;
    float* Zf   = fbase;
    float* H    = Zf + S_ACT;
    float* QKV  = H + S_ACT;            // [ROWS][2304]
    float* CLS  = QKV + 3 * S_ACT;
    float* BQKV = CLS + S_CLS;          // [LAYERS][2304]

    void* hp = nullptr;
    cudaGetSymbolAddress(&hp, g_hscratch);
    __half* P16   = (__half*)hp;
    __half* Z16   = P16 + S_P16;
    __half* Y16   = Z16 + S_Z16;
    __half* MB16  = Y16 + S_Z16;
    __half* PWT   = MB16 + S_MB;
    __half* WQKVT = PWT + S_PWT;        // [LAYERS][2304][768]
    __half* WYT   = WQKVT + S_QKV;
    __half* M1T   = WYT + S_WXT;
    __half* M2T   = M1T + S_M1T;

    cudaFuncSetAttribute(attn_kernel, cudaFuncAttributeMaxDynamicSharedMemorySize, ATTN_SMEM);
    cudaFuncSetAttribute(gemm_old, cudaFuncAttributeMaxDynamicSharedMemorySize, GEMM_SMEM_OLD);
    cudaFuncSetAttribute((const void*)gemm_cp<0, float>,  cudaFuncAttributeMaxDynamicSharedMemorySize, CPH_SMEM);
    cudaFuncSetAttribute((const void*)gemm_cp<1, float>,  cudaFuncAttributeMaxDynamicSharedMemorySize, CPH_SMEM);
    cudaFuncSetAttribute((const void*)gemm_cp<2, __half>, cudaFuncAttributeMaxDynamicSharedMemorySize, CPH_SMEM);

    // Pre-transpose+round weights to fp16 [N][K]; QKV concatenated per layer
    {
        dim3 blk(32, 8);
        const long long W2 = 768LL * 768, QKVL = 2304LL * 768, M = 768LL * 3072;
        transpose_w<<<dim3(24, 24, 1),  blk>>>(patch_w, PWT, 768, 768, 0, 0);
        transpose_w<<<dim3(24, 24, 12), blk>>>(wq, WQKVT,              768, 768, W2, QKVL);
        transpose_w<<<dim3(24, 24, 12), blk>>>(wk, WQKVT + 768 * 768,  768, 768, W2, QKVL);
        transpose_w<<<dim3(24, 24, 12), blk>>>(wv, WQKVT + 1536 * 768, 768, 768, W2, QKVL);
        transpose_w<<<dim3(24, 24, 12), blk>>>(wy, WYT, 768, 768, W2, W2);
        transpose_w<<<dim3(96, 24, 12), blk>>>(m1w, M1T, 768, 3072, M, M);
        transpose_w<<<dim3(24, 96, 12), blk>>>(m2w, M2T, 3072, 768, M, M);
        concat_bias<<<(LAYERS * 2304 + 255) / 256, 256>>>(bq, bk, bv, BQKV);
    }

    // patch embed
    gather_patches<<<(PROWS * DIM + 255) / 256, 256>>>(x, P16);
    gemm_cp<0, float><<<dim3(6, 49), 256, CPH_SMEM>>>(P16, PWT, patch_b, nullptr, Zf, PROWS, 768, 768);
    assemble_h<<<(ROWS * DIM + 255) / 256, 256>>>(Zf, cls_t, pos, H);

    const dim3 gqkv(18, 50);  // N=2304 fused QKV
    const dim3 gp(6, 50);     // N=768
    const dim3 gm1(24, 50);   // N=3072
    for (int l = 0; l < LAYERS; l++) {
        const size_t wo = (size_t)l * 768 * 768;
        const size_t qo = (size_t)l * 2304 * 768;
        const size_t mo = (size_t)l * 768 * 3072;
        ln_kernel<__half><<<ROWS, 256>>>(H, Z16, ln1w + l * 768, ln1b + l * 768, 768);
        gemm_cp<0, float><<<gqkv, 256, CPH_SMEM>>>(Z16, WQKVT + qo, BQKV + l * 2304, nullptr, QKV, ROWS, 2304, 768);
        attn_kernel<<<dim3(12, 32), 256, ATTN_SMEM>>>(QKV, QKV + 768, QKV + 1536, Y16, 2304);
        gemm_cp<1, float><<<gp, 256, CPH_SMEM>>>(Y16, WYT + wo, by + l * 768, H, H, ROWS, 768, 768);
        ln_kernel<__half><<<ROWS, 256>>>(H, Z16, ln2w + l * 768, ln2b + l * 768, 768);
        gemm_cp<2, __half><<<gm1, 256, CPH_SMEM>>>(Z16, M1T + mo, m1b + (size_t)l * 3072, nullptr, MB16, ROWS, 3072, 768);
        gemm_cp<1, float><<<gp, 256, CPH_SMEM>>>(MB16, M2T + mo, m2b + l * 768, H, H, ROWS, 768, 3072);
    }

    // head: LN (fp32 out) over CLS rows, then [32,768]@[768,1000]
    ln_kernel<float><<<32, 256>>>(H, CLS, hlnw, hlnb, (long long)197 * 768);
    gemm_old<<<dim3(8, 1), 256, GEMM_SMEM_OLD>>>(CLS, hw, hb, out, 32, NCLS, 768);
}